// round 1
// baseline (speedup 1.0000x reference)
#include <cuda_runtime.h>
#include <math.h>

#define NN 100000
#define EE 1600000
#define HH 128
#define CC 40

// ---- scratch (device globals; no allocation allowed) ----
__device__ float g_agg[(size_t)NN * HH];
__device__ float g_x1 [(size_t)NN * HH];
__device__ float g_x2 [(size_t)NN * HH];
__device__ int   g_cnt[NN];
__device__ int   g_off[NN + 1];
__device__ int   g_cur[NN];
__device__ int   g_srcs[EE];

// ---------------- CSR build ----------------
__global__ void zero_cnt_k() {
    int i = blockIdx.x * blockDim.x + threadIdx.x;
    if (i < NN) g_cnt[i] = 0;
}

__global__ void hist_k(const int* __restrict__ ei) {
    int e = blockIdx.x * blockDim.x + threadIdx.x;
    if (e < EE) atomicAdd(&g_cnt[ei[EE + e]], 1);
}

__global__ void scan_k() {
    __shared__ int wsum[32];
    __shared__ int s_carry;
    const int t = threadIdx.x;
    const int lane = t & 31, wid = t >> 5;
    if (t == 0) s_carry = 0;
    __syncthreads();
    for (int base = 0; base < NN; base += 1024) {
        int i = base + t;
        int v = (i < NN) ? g_cnt[i] : 0;
        int x = v;
        #pragma unroll
        for (int d = 1; d < 32; d <<= 1) {
            int y = __shfl_up_sync(0xffffffffu, x, d);
            if (lane >= d) x += y;
        }
        if (lane == 31) wsum[wid] = x;
        __syncthreads();
        if (wid == 0) {
            int w = wsum[lane];
            #pragma unroll
            for (int d = 1; d < 32; d <<= 1) {
                int y = __shfl_up_sync(0xffffffffu, w, d);
                if (lane >= d) w += y;
            }
            wsum[lane] = w;
        }
        __syncthreads();
        int incl = x + (wid ? wsum[wid - 1] : 0);
        int carry = s_carry;
        if (i < NN) {
            int excl = carry + incl - v;
            g_off[i] = excl;
            g_cur[i] = excl;
        }
        __syncthreads();
        if (t == 1023) s_carry = carry + incl;
        __syncthreads();
    }
    if (t == 0) g_off[NN] = s_carry;
}

__global__ void fill_k(const int* __restrict__ ei) {
    int e = blockIdx.x * blockDim.x + threadIdx.x;
    if (e < EE) {
        int src = ei[e];
        int dst = ei[EE + e];
        int pos = atomicAdd(&g_cur[dst], 1);
        g_srcs[pos] = src;
    }
}

// ---------------- edge aggregation (CSR gather, no atomics) ----------------
// one block (128 threads) per node; thread t owns feature column t
__global__ void agg_k(const float* __restrict__ x, int use_x) {
    const float* __restrict__ in = use_x ? x : g_x1;
    const int i = blockIdx.x;
    const int t = threadIdx.x;
    const int s = g_off[i], e = g_off[i + 1];
    float acc0 = 0.f, acc1 = 0.f;
    int p = s;
    for (; p + 1 < e; p += 2) {
        int s0 = g_srcs[p];
        int s1 = g_srcs[p + 1];
        acc0 += in[(size_t)s0 * HH + t];
        acc1 += in[(size_t)s1 * HH + t];
    }
    if (p < e) acc0 += in[(size_t)g_srcs[p] * HH + t];
    g_agg[(size_t)i * HH + t] = acc0 + acc1;
}

// ---------------- fused dual GEMM: C = relu(A1@B1 + A2@B2 + bias) ----------------
// A1 = g_agg [M,128], A2 = x or g_x1, B1/B2 = 128x128 row-major, out g_x1/g_x2
// BM=128, BN=128, BK=16, 256 threads, TM=TN=8
__global__ __launch_bounds__(256) void gemm_dual_relu_k(
    const float* __restrict__ x,
    const float* __restrict__ B1, const float* __restrict__ B2,
    const float* __restrict__ bias, int layer)
{
    const float* __restrict__ A1 = g_agg;
    const float* __restrict__ A2 = (layer == 1) ? x : g_x1;
    float* __restrict__ C = (layer == 1) ? g_x1 : g_x2;

    __shared__ float sA1[16][128];
    __shared__ float sA2[16][128];
    __shared__ float sB1[16][128];
    __shared__ float sB2[16][128];

    const int t  = threadIdx.x;
    const int m0 = blockIdx.x * 128;
    const int ty = t >> 4;     // 0..15 -> rows ty*8..
    const int tx = t & 15;     // 0..15 -> cols tx*8..

    float acc[8][8];
    #pragma unroll
    for (int i = 0; i < 8; i++)
        #pragma unroll
        for (int j = 0; j < 8; j++) acc[i][j] = 0.f;

    const int ar = t >> 2;         // 0..63 (+q*64)
    const int ak = (t & 3) * 4;    // 0,4,8,12
    const int bk = t >> 4;         // 0..15
    const int bn = (t & 15) * 4;   // (+q*64)

    for (int k0 = 0; k0 < 128; k0 += 16) {
        #pragma unroll
        for (int q = 0; q < 2; q++) {
            int r = ar + q * 64;
            int grow = m0 + r;
            float4 v1, v2;
            if (grow < NN) {
                v1 = *(const float4*)(A1 + (size_t)grow * 128 + k0 + ak);
                v2 = *(const float4*)(A2 + (size_t)grow * 128 + k0 + ak);
            } else {
                v1 = make_float4(0.f, 0.f, 0.f, 0.f);
                v2 = v1;
            }
            sA1[ak + 0][r] = v1.x; sA1[ak + 1][r] = v1.y;
            sA1[ak + 2][r] = v1.z; sA1[ak + 3][r] = v1.w;
            sA2[ak + 0][r] = v2.x; sA2[ak + 1][r] = v2.y;
            sA2[ak + 2][r] = v2.z; sA2[ak + 3][r] = v2.w;

            int nb = bn + q * 64;
            *(float4*)&sB1[bk][nb] = *(const float4*)(B1 + (size_t)(k0 + bk) * 128 + nb);
            *(float4*)&sB2[bk][nb] = *(const float4*)(B2 + (size_t)(k0 + bk) * 128 + nb);
        }
        __syncthreads();

        #pragma unroll
        for (int kk = 0; kk < 16; ++kk) {
            float a1[8], a2[8], b1[8], b2[8];
            *(float4*)&a1[0] = *(const float4*)&sA1[kk][ty * 8];
            *(float4*)&a1[4] = *(const float4*)&sA1[kk][ty * 8 + 4];
            *(float4*)&a2[0] = *(const float4*)&sA2[kk][ty * 8];
            *(float4*)&a2[4] = *(const float4*)&sA2[kk][ty * 8 + 4];
            *(float4*)&b1[0] = *(const float4*)&sB1[kk][tx * 8];
            *(float4*)&b1[4] = *(const float4*)&sB1[kk][tx * 8 + 4];
            *(float4*)&b2[0] = *(const float4*)&sB2[kk][tx * 8];
            *(float4*)&b2[4] = *(const float4*)&sB2[kk][tx * 8 + 4];
            #pragma unroll
            for (int i = 0; i < 8; i++)
                #pragma unroll
                for (int j = 0; j < 8; j++) {
                    acc[i][j] += a1[i] * b1[j];
                    acc[i][j] += a2[i] * b2[j];
                }
        }
        __syncthreads();
    }

    #pragma unroll
    for (int i = 0; i < 8; i++) {
        int row = m0 + ty * 8 + i;
        if (row < NN) {
            #pragma unroll
            for (int j = 0; j < 8; j++) {
                float v = acc[i][j] + bias[tx * 8 + j];
                C[(size_t)row * 128 + tx * 8 + j] = v > 0.f ? v : 0.f;
            }
        }
    }
}

// ---------------- logits GEMM: out = [x1|x2] @ W_lin + b_lin ----------------
// M=100k, N=40, K=256. BM=64, BN=40, BK=16, 128 threads, TM=4, TN=5
__global__ __launch_bounds__(128) void gemm_logits_k(
    const float* __restrict__ W, const float* __restrict__ bias,
    float* __restrict__ out)
{
    __shared__ float sA[16][64];
    __shared__ float sB[16][40];

    const int t  = threadIdx.x;
    const int m0 = blockIdx.x * 64;
    const int ty = t >> 3;   // 0..15 -> rows ty*4..
    const int tx = t & 7;    // 0..7  -> cols tx*5..

    float acc[4][5];
    #pragma unroll
    for (int i = 0; i < 4; i++)
        #pragma unroll
        for (int j = 0; j < 5; j++) acc[i][j] = 0.f;

    const int ar = t >> 2;        // 0..31 (+q*32)
    const int ak = (t & 3) * 4;

    for (int k0 = 0; k0 < 256; k0 += 16) {
        const float* __restrict__ A = (k0 < 128) ? g_x1 : g_x2;
        const int kbase = k0 & 127;
        #pragma unroll
        for (int q = 0; q < 2; q++) {
            int r = ar + q * 32;
            int grow = m0 + r;
            float4 v = (grow < NN)
                ? *(const float4*)(A + (size_t)grow * 128 + kbase + ak)
                : make_float4(0.f, 0.f, 0.f, 0.f);
            sA[ak + 0][r] = v.x; sA[ak + 1][r] = v.y;
            sA[ak + 2][r] = v.z; sA[ak + 3][r] = v.w;
        }
        #pragma unroll
        for (int q = 0; q < 5; q++) {
            int idx = q * 128 + t;      // 0..639 = 16*40
            int kb = idx / 40, nb = idx % 40;
            sB[kb][nb] = W[(size_t)(k0 + kb) * 40 + nb];
        }
        __syncthreads();

        #pragma unroll
        for (int kk = 0; kk < 16; ++kk) {
            float a[4], b[5];
            #pragma unroll
            for (int i = 0; i < 4; i++) a[i] = sA[kk][ty * 4 + i];
            #pragma unroll
            for (int j = 0; j < 5; j++) b[j] = sB[kk][tx * 5 + j];
            #pragma unroll
            for (int i = 0; i < 4; i++)
                #pragma unroll
                for (int j = 0; j < 5; j++) acc[i][j] += a[i] * b[j];
        }
        __syncthreads();
    }

    #pragma unroll
    for (int i = 0; i < 4; i++) {
        int row = m0 + ty * 4 + i;
        if (row < NN) {
            #pragma unroll
            for (int j = 0; j < 5; j++)
                out[(size_t)row * 40 + tx * 5 + j] = acc[i][j] + bias[tx * 5 + j];
        }
    }
}

// ---------------- log_softmax over 40 cols, warp per row, in-place ----------------
__global__ void logsoftmax_k(float* __restrict__ out) {
    int warp = (blockIdx.x * blockDim.x + threadIdx.x) >> 5;
    int lane = threadIdx.x & 31;
    if (warp >= NN) return;
    float* row = out + (size_t)warp * 40;
    float v0 = row[lane];
    float v1 = (lane < 8) ? row[32 + lane] : -3.402823e38f;
    float m = fmaxf(v0, v1);
    #pragma unroll
    for (int d = 16; d; d >>= 1) m = fmaxf(m, __shfl_xor_sync(0xffffffffu, m, d));
    float s = expf(v0 - m) + ((lane < 8) ? expf(v1 - m) : 0.f);
    #pragma unroll
    for (int d = 16; d; d >>= 1) s += __shfl_xor_sync(0xffffffffu, s, d);
    float l = m + logf(s);
    row[lane] = v0 - l;
    if (lane < 8) row[32 + lane] = v1 - l;
}

// ---------------- launch ----------------
extern "C" void kernel_launch(void* const* d_in, const int* in_sizes, int n_in,
                              void* d_out, int out_size) {
    const float* x      = (const float*)d_in[0];
    const int*   ei     = (const int*)  d_in[1];
    const float* Wrel1  = (const float*)d_in[2];
    const float* brel1  = (const float*)d_in[3];
    const float* Wroot1 = (const float*)d_in[4];
    const float* Wrel2  = (const float*)d_in[5];
    const float* brel2  = (const float*)d_in[6];
    const float* Wroot2 = (const float*)d_in[7];
    const float* Wlin   = (const float*)d_in[8];
    const float* blin   = (const float*)d_in[9];
    float* out = (float*)d_out;

    // CSR build (reused by both layers)
    zero_cnt_k<<<(NN + 255) / 256, 256>>>();
    hist_k<<<(EE + 255) / 256, 256>>>(ei);
    scan_k<<<1, 1024>>>();
    fill_k<<<(EE + 255) / 256, 256>>>(ei);

    // layer 1
    agg_k<<<NN, 128>>>(x, 1);
    gemm_dual_relu_k<<<(NN + 127) / 128, 256>>>(x, Wrel1, Wroot1, brel1, 1);

    // layer 2
    agg_k<<<NN, 128>>>(x, 0);
    gemm_dual_relu_k<<<(NN + 127) / 128, 256>>>(x, Wrel2, Wroot2, brel2, 2);

    // head
    gemm_logits_k<<<(NN + 63) / 64, 128>>>(Wlin, blin, out);
    logsoftmax_k<<<(NN * 32 + 255) / 256, 256>>>(out);
}

// round 2
// speedup vs baseline: 1.4659x; 1.4659x over previous
#include <cuda_runtime.h>
#include <math.h>
#include <stdint.h>

#define NN 100000
#define EE 1600000
#define HH 128
#define CC 40

// ---- scratch (device globals; no allocation allowed) ----
__device__ float g_agg[(size_t)NN * HH];
__device__ float g_x1 [(size_t)NN * HH];
__device__ float g_x2 [(size_t)NN * HH];
__device__ int   g_cnt[NN];
__device__ int   g_off[NN + 1];
__device__ int   g_cur[NN];
__device__ int   g_srcs[EE];

// ---------------- CSR build ----------------
__global__ void zero_cnt_k() {
    int i = blockIdx.x * blockDim.x + threadIdx.x;
    if (i < NN) g_cnt[i] = 0;
}

__global__ void hist_k(const int* __restrict__ ei) {
    int e = blockIdx.x * blockDim.x + threadIdx.x;
    if (e < EE) atomicAdd(&g_cnt[ei[EE + e]], 1);
}

__global__ void scan_k() {
    __shared__ int wsum[32];
    __shared__ int s_carry;
    const int t = threadIdx.x;
    const int lane = t & 31, wid = t >> 5;
    if (t == 0) s_carry = 0;
    __syncthreads();
    for (int base = 0; base < NN; base += 1024) {
        int i = base + t;
        int v = (i < NN) ? g_cnt[i] : 0;
        int x = v;
        #pragma unroll
        for (int d = 1; d < 32; d <<= 1) {
            int y = __shfl_up_sync(0xffffffffu, x, d);
            if (lane >= d) x += y;
        }
        if (lane == 31) wsum[wid] = x;
        __syncthreads();
        if (wid == 0) {
            int w = wsum[lane];
            #pragma unroll
            for (int d = 1; d < 32; d <<= 1) {
                int y = __shfl_up_sync(0xffffffffu, w, d);
                if (lane >= d) w += y;
            }
            wsum[lane] = w;
        }
        __syncthreads();
        int incl = x + (wid ? wsum[wid - 1] : 0);
        int carry = s_carry;
        if (i < NN) {
            int excl = carry + incl - v;
            g_off[i] = excl;
            g_cur[i] = excl;
        }
        __syncthreads();
        if (t == 1023) s_carry = carry + incl;
        __syncthreads();
    }
    if (t == 0) g_off[NN] = s_carry;
}

__global__ void fill_k(const int* __restrict__ ei) {
    int e = blockIdx.x * blockDim.x + threadIdx.x;
    if (e < EE) {
        int src = ei[e];
        int dst = ei[EE + e];
        int pos = atomicAdd(&g_cur[dst], 1);
        g_srcs[pos] = src;
    }
}

// ---------------- edge aggregation (CSR gather, no atomics) ----------------
__global__ void agg_k(const float* __restrict__ x, int use_x) {
    const float* __restrict__ in = use_x ? x : g_x1;
    const int i = blockIdx.x;
    const int t = threadIdx.x;
    const int s = g_off[i], e = g_off[i + 1];
    float acc0 = 0.f, acc1 = 0.f;
    int p = s;
    for (; p + 1 < e; p += 2) {
        int s0 = g_srcs[p];
        int s1 = g_srcs[p + 1];
        acc0 += in[(size_t)s0 * HH + t];
        acc1 += in[(size_t)s1 * HH + t];
    }
    if (p < e) acc0 += in[(size_t)g_srcs[p] * HH + t];
    g_agg[(size_t)i * HH + t] = acc0 + acc1;
}

// ---------------- TF32 helpers ----------------
__device__ __forceinline__ float cvt_tf32(float x) {
    uint32_t u;
    asm("cvt.rna.tf32.f32 %0, %1;" : "=r"(u) : "f"(x));
    return __uint_as_float(u);
}

__device__ __forceinline__ void mma_tf32(float* d, const uint32_t* a, const uint32_t* b) {
    asm volatile(
        "mma.sync.aligned.m16n8k8.row.col.f32.tf32.tf32.f32 "
        "{%0,%1,%2,%3}, {%4,%5,%6,%7}, {%8,%9}, {%0,%1,%2,%3};\n"
        : "+f"(d[0]), "+f"(d[1]), "+f"(d[2]), "+f"(d[3])
        : "r"(a[0]), "r"(a[1]), "r"(a[2]), "r"(a[3]),
          "r"(b[0]), "r"(b[1]));
}

// ---------------- fused dual GEMM (TF32 tensor cores) ----------------
// C = relu([agg | xsrc] @ [Brel ; Broot] + bias), M=NN, N=128, K=256
// BM=128, BN=128, BK=32, 256 threads (8 warps, 2x4), warp tile 64x32
__global__ __launch_bounds__(256) void gemm_dual_tf32_k(
    const float* __restrict__ x,
    const float* __restrict__ B1, const float* __restrict__ B2,
    const float* __restrict__ bias, int layer)
{
    const float* __restrict__ A1 = g_agg;
    const float* __restrict__ A2 = (layer == 1) ? x : g_x1;
    float* __restrict__ C = (layer == 1) ? g_x1 : g_x2;

    __shared__ float sA[128][36];   // [m][k], stride 36 -> bank = 4m+k (conflict-free frags)
    __shared__ float sB[32][136];   // [k][n], stride 136 -> bank = 8k+n (conflict-free frags)

    const int t    = threadIdx.x;
    const int lane = t & 31;
    const int wid  = t >> 5;
    const int wm   = wid >> 2;      // 0..1
    const int wn   = wid & 3;       // 0..3
    const int m0   = blockIdx.x * 128;

    float acc[4][4][4];
    #pragma unroll
    for (int mt = 0; mt < 4; mt++)
        #pragma unroll
        for (int nt = 0; nt < 4; nt++)
            #pragma unroll
            for (int q = 0; q < 4; q++) acc[mt][nt][q] = 0.f;

    #pragma unroll 1
    for (int s = 0; s < 8; ++s) {
        const float* __restrict__ Asrc = (s < 4) ? A1 : A2;
        const float* __restrict__ Bsrc = (s < 4) ? B1 : B2;
        const int kb = (s & 3) * 32;

        // stage A tile: 128x32, 4 float4 per thread, coalesced
        #pragma unroll
        for (int q = 0; q < 4; ++q) {
            int idx = q * 256 + t;
            int r   = idx >> 3;
            int c4  = (idx & 7) * 4;
            int grow = m0 + r;
            float4 v = (grow < NN)
                ? *(const float4*)(Asrc + (size_t)grow * 128 + kb + c4)
                : make_float4(0.f, 0.f, 0.f, 0.f);
            v.x = cvt_tf32(v.x); v.y = cvt_tf32(v.y);
            v.z = cvt_tf32(v.z); v.w = cvt_tf32(v.w);
            *(float4*)&sA[r][c4] = v;
        }
        // stage B tile: 32x128, 4 float4 per thread, coalesced
        #pragma unroll
        for (int q = 0; q < 4; ++q) {
            int idx = q * 256 + t;
            int kr  = idx >> 5;
            int c4  = (idx & 31) * 4;
            float4 v = *(const float4*)(Bsrc + (size_t)(kb + kr) * 128 + c4);
            v.x = cvt_tf32(v.x); v.y = cvt_tf32(v.y);
            v.z = cvt_tf32(v.z); v.w = cvt_tf32(v.w);
            *(float4*)&sB[kr][c4] = v;
        }
        __syncthreads();

        #pragma unroll
        for (int kk = 0; kk < 4; ++kk) {
            uint32_t a[4][4], b[4][2];
            const int krow = kk * 8;
            const int ar0  = wm * 64 + (lane >> 2);
            const int ac   = krow + (lane & 3);
            #pragma unroll
            for (int mt = 0; mt < 4; ++mt) {
                int r = ar0 + mt * 16;
                a[mt][0] = __float_as_uint(sA[r    ][ac    ]);
                a[mt][1] = __float_as_uint(sA[r + 8][ac    ]);
                a[mt][2] = __float_as_uint(sA[r    ][ac + 4]);
                a[mt][3] = __float_as_uint(sA[r + 8][ac + 4]);
            }
            const int br  = krow + (lane & 3);
            const int bc0 = wn * 32 + (lane >> 2);
            #pragma unroll
            for (int nt = 0; nt < 4; ++nt) {
                b[nt][0] = __float_as_uint(sB[br    ][bc0 + nt * 8]);
                b[nt][1] = __float_as_uint(sB[br + 4][bc0 + nt * 8]);
            }
            #pragma unroll
            for (int mt = 0; mt < 4; ++mt)
                #pragma unroll
                for (int nt = 0; nt < 4; ++nt)
                    mma_tf32(acc[mt][nt], a[mt], b[nt]);
        }
        __syncthreads();
    }

    // epilogue: bias + relu, float2 stores
    const int r0 = m0 + wm * 64 + (lane >> 2);
    const int c0 = wn * 32 + 2 * (lane & 3);
    #pragma unroll
    for (int nt = 0; nt < 4; ++nt) {
        int col = c0 + nt * 8;
        float bb0 = bias[col], bb1 = bias[col + 1];
        #pragma unroll
        for (int mt = 0; mt < 4; ++mt) {
            int row = r0 + mt * 16;
            if (row < NN) {
                float v0 = fmaxf(acc[mt][nt][0] + bb0, 0.f);
                float v1 = fmaxf(acc[mt][nt][1] + bb1, 0.f);
                *(float2*)&C[(size_t)row * 128 + col] = make_float2(v0, v1);
            }
            if (row + 8 < NN) {
                float v2 = fmaxf(acc[mt][nt][2] + bb0, 0.f);
                float v3 = fmaxf(acc[mt][nt][3] + bb1, 0.f);
                *(float2*)&C[(size_t)(row + 8) * 128 + col] = make_float2(v2, v3);
            }
        }
    }
}

// ---------------- logits GEMM: out = [x1|x2] @ W_lin + b_lin (fp32) ----------------
__global__ __launch_bounds__(128) void gemm_logits_k(
    const float* __restrict__ W, const float* __restrict__ bias,
    float* __restrict__ out)
{
    __shared__ float sA[16][64];
    __shared__ float sB[16][40];

    const int t  = threadIdx.x;
    const int m0 = blockIdx.x * 64;
    const int ty = t >> 3;
    const int tx = t & 7;

    float acc[4][5];
    #pragma unroll
    for (int i = 0; i < 4; i++)
        #pragma unroll
        for (int j = 0; j < 5; j++) acc[i][j] = 0.f;

    const int ar = t >> 2;
    const int ak = (t & 3) * 4;

    for (int k0 = 0; k0 < 256; k0 += 16) {
        const float* __restrict__ A = (k0 < 128) ? g_x1 : g_x2;
        const int kbase = k0 & 127;
        #pragma unroll
        for (int q = 0; q < 2; q++) {
            int r = ar + q * 32;
            int grow = m0 + r;
            float4 v = (grow < NN)
                ? *(const float4*)(A + (size_t)grow * 128 + kbase + ak)
                : make_float4(0.f, 0.f, 0.f, 0.f);
            sA[ak + 0][r] = v.x; sA[ak + 1][r] = v.y;
            sA[ak + 2][r] = v.z; sA[ak + 3][r] = v.w;
        }
        #pragma unroll
        for (int q = 0; q < 5; q++) {
            int idx = q * 128 + t;
            int kb = idx / 40, nb = idx % 40;
            sB[kb][nb] = W[(size_t)(k0 + kb) * 40 + nb];
        }
        __syncthreads();

        #pragma unroll
        for (int kk = 0; kk < 16; ++kk) {
            float a[4], b[5];
            #pragma unroll
            for (int i = 0; i < 4; i++) a[i] = sA[kk][ty * 4 + i];
            #pragma unroll
            for (int j = 0; j < 5; j++) b[j] = sB[kk][tx * 5 + j];
            #pragma unroll
            for (int i = 0; i < 4; i++)
                #pragma unroll
                for (int j = 0; j < 5; j++) acc[i][j] += a[i] * b[j];
        }
        __syncthreads();
    }

    #pragma unroll
    for (int i = 0; i < 4; i++) {
        int row = m0 + ty * 4 + i;
        if (row < NN) {
            #pragma unroll
            for (int j = 0; j < 5; j++)
                out[(size_t)row * 40 + tx * 5 + j] = acc[i][j] + bias[tx * 5 + j];
        }
    }
}

// ---------------- log_softmax over 40 cols, warp per row, in-place ----------------
__global__ void logsoftmax_k(float* __restrict__ out) {
    int warp = (blockIdx.x * blockDim.x + threadIdx.x) >> 5;
    int lane = threadIdx.x & 31;
    if (warp >= NN) return;
    float* row = out + (size_t)warp * 40;
    float v0 = row[lane];
    float v1 = (lane < 8) ? row[32 + lane] : -3.402823e38f;
    float m = fmaxf(v0, v1);
    #pragma unroll
    for (int d = 16; d; d >>= 1) m = fmaxf(m, __shfl_xor_sync(0xffffffffu, m, d));
    float s = expf(v0 - m) + ((lane < 8) ? expf(v1 - m) : 0.f);
    #pragma unroll
    for (int d = 16; d; d >>= 1) s += __shfl_xor_sync(0xffffffffu, s, d);
    float l = m + logf(s);
    row[lane] = v0 - l;
    if (lane < 8) row[32 + lane] = v1 - l;
}

// ---------------- launch ----------------
extern "C" void kernel_launch(void* const* d_in, const int* in_sizes, int n_in,
                              void* d_out, int out_size) {
    const float* x      = (const float*)d_in[0];
    const int*   ei     = (const int*)  d_in[1];
    const float* Wrel1  = (const float*)d_in[2];
    const float* brel1  = (const float*)d_in[3];
    const float* Wroot1 = (const float*)d_in[4];
    const float* Wrel2  = (const float*)d_in[5];
    const float* brel2  = (const float*)d_in[6];
    const float* Wroot2 = (const float*)d_in[7];
    const float* Wlin   = (const float*)d_in[8];
    const float* blin   = (const float*)d_in[9];
    float* out = (float*)d_out;

    // CSR build (reused by both layers)
    zero_cnt_k<<<(NN + 255) / 256, 256>>>();
    hist_k<<<(EE + 255) / 256, 256>>>(ei);
    scan_k<<<1, 1024>>>();
    fill_k<<<(EE + 255) / 256, 256>>>(ei);

    // layer 1
    agg_k<<<NN, 128>>>(x, 1);
    gemm_dual_tf32_k<<<(NN + 127) / 128, 256>>>(x, Wrel1, Wroot1, brel1, 1);

    // layer 2
    agg_k<<<NN, 128>>>(x, 0);
    gemm_dual_tf32_k<<<(NN + 127) / 128, 256>>>(x, Wrel2, Wroot2, brel2, 2);

    // head
    gemm_logits_k<<<(NN + 63) / 64, 128>>>(Wlin, blin, out);
    logsoftmax_k<<<(NN * 32 + 255) / 256, 256>>>(out);
}

// round 3
// speedup vs baseline: 1.7379x; 1.1856x over previous
#include <cuda_runtime.h>
#include <cuda_fp16.h>
#include <math.h>
#include <stdint.h>

#define NN 100000
#define EE 1600000
#define HH 128
#define CC 40

// ---- scratch (device globals; no allocation allowed) ----
__device__ float  g_agg[(size_t)NN * HH];
__device__ float  g_x1 [(size_t)NN * HH];
__device__ float  g_x2 [(size_t)NN * HH];
__device__ __half g_xh [(size_t)NN * HH];
__device__ __half g_x1h[(size_t)NN * HH];
__device__ int    g_cnt[NN];
__device__ int    g_off[NN + 1];
__device__ int    g_cur[NN];
__device__ int    g_srcs[EE];
__device__ int    g_bsum[256];

// ---------------- CSR build ----------------
__global__ void zero_cnt_k() {
    int i = blockIdx.x * blockDim.x + threadIdx.x;
    if (i < NN) g_cnt[i] = 0;
}

__global__ void hist_k(const int* __restrict__ ei) {
    int e = blockIdx.x * blockDim.x + threadIdx.x;
    if (e < EE) atomicAdd(&g_cnt[ei[EE + e]], 1);
}

// block-local exclusive scan over 512-elem chunks; block totals -> g_bsum
__global__ __launch_bounds__(512) void scan1_k() {
    __shared__ int wsum[16];
    const int t = threadIdx.x, lane = t & 31, wid = t >> 5;
    const int i = blockIdx.x * 512 + t;
    int v = (i < NN) ? g_cnt[i] : 0;
    int x = v;
    #pragma unroll
    for (int d = 1; d < 32; d <<= 1) {
        int y = __shfl_up_sync(0xffffffffu, x, d);
        if (lane >= d) x += y;
    }
    if (lane == 31) wsum[wid] = x;
    __syncthreads();
    if (wid == 0 && lane < 16) {
        int w = wsum[lane];
        #pragma unroll
        for (int d = 1; d < 16; d <<= 1) {
            int y = __shfl_up_sync(0xffffu, w, d);
            if (lane >= d) w += y;
        }
        wsum[lane] = w;
    }
    __syncthreads();
    int incl = x + (wid ? wsum[wid - 1] : 0);
    if (i < NN) g_off[i] = incl - v;
    if (t == 511) g_bsum[blockIdx.x] = incl;
}

// exclusive scan of block totals (<=256 values), single block
__global__ __launch_bounds__(256) void scan2_k(int nblk) {
    __shared__ int wsum[8];
    const int t = threadIdx.x, lane = t & 31, wid = t >> 5;
    int v = (t < nblk) ? g_bsum[t] : 0;
    int x = v;
    #pragma unroll
    for (int d = 1; d < 32; d <<= 1) {
        int y = __shfl_up_sync(0xffffffffu, x, d);
        if (lane >= d) x += y;
    }
    if (lane == 31) wsum[wid] = x;
    __syncthreads();
    if (wid == 0 && lane < 8) {
        int w = wsum[lane];
        #pragma unroll
        for (int d = 1; d < 8; d <<= 1) {
            int y = __shfl_up_sync(0xffu, w, d);
            if (lane >= d) w += y;
        }
        wsum[lane] = w;
    }
    __syncthreads();
    int incl = x + (wid ? wsum[wid - 1] : 0);
    if (t < nblk) g_bsum[t] = incl - v;
}

__global__ void scan3_k() {
    int i = blockIdx.x * blockDim.x + threadIdx.x;
    if (i < NN) {
        int o = g_off[i] + g_bsum[i >> 9];
        g_off[i] = o;
        g_cur[i] = o;
    }
    if (i == 0) g_off[NN] = EE;
}

__global__ void fill_k(const int* __restrict__ ei) {
    int e = blockIdx.x * blockDim.x + threadIdx.x;
    if (e < EE) {
        int src = ei[e];
        int dst = ei[EE + e];
        int pos = atomicAdd(&g_cur[dst], 1);
        g_srcs[pos] = src;
    }
}

// ---------------- fp32 -> fp16 convert of input x ----------------
__global__ void cvt_half_k(const float* __restrict__ x) {
    int i = blockIdx.x * blockDim.x + threadIdx.x;   // over NN*HH/4
    if (i < NN * HH / 4) {
        float4 v = *(const float4*)(x + (size_t)i * 4);
        __half2* o = (__half2*)(g_xh + (size_t)i * 4);
        o[0] = __floats2half2_rn(v.x, v.y);
        o[1] = __floats2half2_rn(v.z, v.w);
    }
}

// ---------------- edge aggregation (CSR gather, fp16 operands, fp32 acc) ----------------
__global__ void agg_h_k(int layer) {
    const __half* __restrict__ in = (layer == 1) ? g_xh : g_x1h;
    const int i = blockIdx.x;
    const int t = threadIdx.x;
    const int s = g_off[i], e = g_off[i + 1];
    float acc0 = 0.f, acc1 = 0.f;
    int p = s;
    for (; p + 1 < e; p += 2) {
        int s0 = g_srcs[p];
        int s1 = g_srcs[p + 1];
        acc0 += __half2float(in[(size_t)s0 * HH + t]);
        acc1 += __half2float(in[(size_t)s1 * HH + t]);
    }
    if (p < e) acc0 += __half2float(in[(size_t)g_srcs[p] * HH + t]);
    g_agg[(size_t)i * HH + t] = acc0 + acc1;
}

// ---------------- TF32 helpers ----------------
__device__ __forceinline__ float cvt_tf32(float x) {
    uint32_t u;
    asm("cvt.rna.tf32.f32 %0, %1;" : "=r"(u) : "f"(x));
    return __uint_as_float(u);
}

__device__ __forceinline__ void mma_tf32(float* d, const uint32_t* a, const uint32_t* b) {
    asm volatile(
        "mma.sync.aligned.m16n8k8.row.col.f32.tf32.tf32.f32 "
        "{%0,%1,%2,%3}, {%4,%5,%6,%7}, {%8,%9}, {%0,%1,%2,%3};\n"
        : "+f"(d[0]), "+f"(d[1]), "+f"(d[2]), "+f"(d[3])
        : "r"(a[0]), "r"(a[1]), "r"(a[2]), "r"(a[3]),
          "r"(b[0]), "r"(b[1]));
}

// ---------------- fused dual GEMM (TF32 tensor cores) ----------------
// C = relu([agg | xsrc] @ [Brel ; Broot] + bias), M=NN, N=128, K=256
__global__ __launch_bounds__(256) void gemm_dual_tf32_k(
    const float* __restrict__ x,
    const float* __restrict__ B1, const float* __restrict__ B2,
    const float* __restrict__ bias, int layer)
{
    const float* __restrict__ A1 = g_agg;
    const float* __restrict__ A2 = (layer == 1) ? x : g_x1;
    float* __restrict__ C = (layer == 1) ? g_x1 : g_x2;

    __shared__ float sA[128][36];   // bank(4m+k): conflict-free
    __shared__ float sB[32][136];   // bank(8k+n): conflict-free

    const int t    = threadIdx.x;
    const int lane = t & 31;
    const int wid  = t >> 5;
    const int wm   = wid >> 2;
    const int wn   = wid & 3;
    const int m0   = blockIdx.x * 128;

    float acc[4][4][4];
    #pragma unroll
    for (int mt = 0; mt < 4; mt++)
        #pragma unroll
        for (int nt = 0; nt < 4; nt++)
            #pragma unroll
            for (int q = 0; q < 4; q++) acc[mt][nt][q] = 0.f;

    #pragma unroll 1
    for (int s = 0; s < 8; ++s) {
        const float* __restrict__ Asrc = (s < 4) ? A1 : A2;
        const float* __restrict__ Bsrc = (s < 4) ? B1 : B2;
        const int kb = (s & 3) * 32;

        #pragma unroll
        for (int q = 0; q < 4; ++q) {
            int idx = q * 256 + t;
            int r   = idx >> 3;
            int c4  = (idx & 7) * 4;
            int grow = m0 + r;
            float4 v = (grow < NN)
                ? *(const float4*)(Asrc + (size_t)grow * 128 + kb + c4)
                : make_float4(0.f, 0.f, 0.f, 0.f);
            v.x = cvt_tf32(v.x); v.y = cvt_tf32(v.y);
            v.z = cvt_tf32(v.z); v.w = cvt_tf32(v.w);
            *(float4*)&sA[r][c4] = v;
        }
        #pragma unroll
        for (int q = 0; q < 4; ++q) {
            int idx = q * 256 + t;
            int kr  = idx >> 5;
            int c4  = (idx & 31) * 4;
            float4 v = *(const float4*)(Bsrc + (size_t)(kb + kr) * 128 + c4);
            v.x = cvt_tf32(v.x); v.y = cvt_tf32(v.y);
            v.z = cvt_tf32(v.z); v.w = cvt_tf32(v.w);
            *(float4*)&sB[kr][c4] = v;
        }
        __syncthreads();

        #pragma unroll
        for (int kk = 0; kk < 4; ++kk) {
            uint32_t a[4][4], b[4][2];
            const int krow = kk * 8;
            const int ar0  = wm * 64 + (lane >> 2);
            const int ac   = krow + (lane & 3);
            #pragma unroll
            for (int mt = 0; mt < 4; ++mt) {
                int r = ar0 + mt * 16;
                a[mt][0] = __float_as_uint(sA[r    ][ac    ]);
                a[mt][1] = __float_as_uint(sA[r + 8][ac    ]);
                a[mt][2] = __float_as_uint(sA[r    ][ac + 4]);
                a[mt][3] = __float_as_uint(sA[r + 8][ac + 4]);
            }
            const int br  = krow + (lane & 3);
            const int bc0 = wn * 32 + (lane >> 2);
            #pragma unroll
            for (int nt = 0; nt < 4; ++nt) {
                b[nt][0] = __float_as_uint(sB[br    ][bc0 + nt * 8]);
                b[nt][1] = __float_as_uint(sB[br + 4][bc0 + nt * 8]);
            }
            #pragma unroll
            for (int mt = 0; mt < 4; ++mt)
                #pragma unroll
                for (int nt = 0; nt < 4; ++nt)
                    mma_tf32(acc[mt][nt], a[mt], b[nt]);
        }
        __syncthreads();
    }

    // epilogue: bias + relu; layer 1 also writes fp16 copy for next-layer gather
    const int r0 = m0 + wm * 64 + (lane >> 2);
    const int c0 = wn * 32 + 2 * (lane & 3);
    #pragma unroll
    for (int nt = 0; nt < 4; ++nt) {
        int col = c0 + nt * 8;
        float bb0 = bias[col], bb1 = bias[col + 1];
        #pragma unroll
        for (int mt = 0; mt < 4; ++mt) {
            int row = r0 + mt * 16;
            if (row < NN) {
                float v0 = fmaxf(acc[mt][nt][0] + bb0, 0.f);
                float v1 = fmaxf(acc[mt][nt][1] + bb1, 0.f);
                *(float2*)&C[(size_t)row * 128 + col] = make_float2(v0, v1);
                if (layer == 1)
                    *(__half2*)&g_x1h[(size_t)row * 128 + col] = __floats2half2_rn(v0, v1);
            }
            if (row + 8 < NN) {
                float v2 = fmaxf(acc[mt][nt][2] + bb0, 0.f);
                float v3 = fmaxf(acc[mt][nt][3] + bb1, 0.f);
                *(float2*)&C[(size_t)(row + 8) * 128 + col] = make_float2(v2, v3);
                if (layer == 1)
                    *(__half2*)&g_x1h[(size_t)(row + 8) * 128 + col] = __floats2half2_rn(v2, v3);
            }
        }
    }
}

// ---------------- logits GEMM (TF32) + fused log_softmax ----------------
// out = log_softmax([x1|x2] @ W_lin + b_lin), M=NN, N=40, K=256
// BM=256, 8 warps, warp = 32 rows x 40 cols
__global__ __launch_bounds__(256) void gemm_logits_tf32_k(
    const float* __restrict__ W, const float* __restrict__ bias,
    float* __restrict__ out)
{
    __shared__ float sA[256][36];
    __shared__ float sB[32][40];

    const int t    = threadIdx.x;
    const int lane = t & 31;
    const int w    = t >> 5;
    const int m0   = blockIdx.x * 256;

    float acc[2][5][4];
    #pragma unroll
    for (int mt = 0; mt < 2; mt++)
        #pragma unroll
        for (int nt = 0; nt < 5; nt++)
            #pragma unroll
            for (int q = 0; q < 4; q++) acc[mt][nt][q] = 0.f;

    #pragma unroll 1
    for (int k0 = 0; k0 < 256; k0 += 32) {
        const float* __restrict__ A = (k0 < 128) ? g_x1 : g_x2;
        const int kb = k0 & 127;
        #pragma unroll
        for (int q = 0; q < 8; ++q) {
            int idx = q * 256 + t;
            int r   = idx >> 3;
            int c4  = (idx & 7) * 4;
            int grow = m0 + r;
            float4 v = (grow < NN)
                ? *(const float4*)(A + (size_t)grow * 128 + kb + c4)
                : make_float4(0.f, 0.f, 0.f, 0.f);
            v.x = cvt_tf32(v.x); v.y = cvt_tf32(v.y);
            v.z = cvt_tf32(v.z); v.w = cvt_tf32(v.w);
            *(float4*)&sA[r][c4] = v;
        }
        #pragma unroll
        for (int q = 0; q < 5; ++q) {
            int idx = q * 256 + t;          // 0..1279 = 32*40
            int kr = idx / 40, nb = idx % 40;
            sB[kr][nb] = cvt_tf32(W[(size_t)(k0 + kr) * 40 + nb]);
        }
        __syncthreads();

        #pragma unroll
        for (int kk = 0; kk < 4; ++kk) {
            uint32_t a[2][4], b[5][2];
            const int krow = kk * 8;
            const int ar0  = w * 32 + (lane >> 2);
            const int ac   = krow + (lane & 3);
            #pragma unroll
            for (int mt = 0; mt < 2; ++mt) {
                int r = ar0 + mt * 16;
                a[mt][0] = __float_as_uint(sA[r    ][ac    ]);
                a[mt][1] = __float_as_uint(sA[r + 8][ac    ]);
                a[mt][2] = __float_as_uint(sA[r    ][ac + 4]);
                a[mt][3] = __float_as_uint(sA[r + 8][ac + 4]);
            }
            const int br  = krow + (lane & 3);
            const int bc0 = lane >> 2;
            #pragma unroll
            for (int nt = 0; nt < 5; ++nt) {
                b[nt][0] = __float_as_uint(sB[br    ][bc0 + nt * 8]);
                b[nt][1] = __float_as_uint(sB[br + 4][bc0 + nt * 8]);
            }
            #pragma unroll
            for (int mt = 0; mt < 2; ++mt)
                #pragma unroll
                for (int nt = 0; nt < 5; ++nt)
                    mma_tf32(acc[mt][nt], a[mt], b[nt]);
        }
        __syncthreads();
    }

    // fused epilogue: bias + log_softmax per row (row lives in one lane-quad)
    #pragma unroll
    for (int mt = 0; mt < 2; ++mt) {
        float vA[10], vB[10];
        #pragma unroll
        for (int nt = 0; nt < 5; ++nt) {
            #pragma unroll
            for (int j = 0; j < 2; ++j) {
                int c = nt * 8 + 2 * (lane & 3) + j;
                float bb = bias[c];
                vA[nt * 2 + j] = acc[mt][nt][j]     + bb;
                vB[nt * 2 + j] = acc[mt][nt][2 + j] + bb;
            }
        }
        float mA = vA[0], mB = vB[0];
        #pragma unroll
        for (int k = 1; k < 10; ++k) { mA = fmaxf(mA, vA[k]); mB = fmaxf(mB, vB[k]); }
        mA = fmaxf(mA, __shfl_xor_sync(0xffffffffu, mA, 1));
        mA = fmaxf(mA, __shfl_xor_sync(0xffffffffu, mA, 2));
        mB = fmaxf(mB, __shfl_xor_sync(0xffffffffu, mB, 1));
        mB = fmaxf(mB, __shfl_xor_sync(0xffffffffu, mB, 2));
        float sA_ = 0.f, sB_ = 0.f;
        #pragma unroll
        for (int k = 0; k < 10; ++k) { sA_ += expf(vA[k] - mA); sB_ += expf(vB[k] - mB); }
        sA_ += __shfl_xor_sync(0xffffffffu, sA_, 1);
        sA_ += __shfl_xor_sync(0xffffffffu, sA_, 2);
        sB_ += __shfl_xor_sync(0xffffffffu, sB_, 1);
        sB_ += __shfl_xor_sync(0xffffffffu, sB_, 2);
        float lA = mA + logf(sA_), lB = mB + logf(sB_);

        int rowA = m0 + w * 32 + mt * 16 + (lane >> 2);
        int rowB = rowA + 8;
        #pragma unroll
        for (int nt = 0; nt < 5; ++nt) {
            int c = nt * 8 + 2 * (lane & 3);
            if (rowA < NN)
                *(float2*)&out[(size_t)rowA * 40 + c] =
                    make_float2(vA[nt * 2] - lA, vA[nt * 2 + 1] - lA);
            if (rowB < NN)
                *(float2*)&out[(size_t)rowB * 40 + c] =
                    make_float2(vB[nt * 2] - lB, vB[nt * 2 + 1] - lB);
        }
    }
}

// ---------------- launch ----------------
extern "C" void kernel_launch(void* const* d_in, const int* in_sizes, int n_in,
                              void* d_out, int out_size) {
    const float* x      = (const float*)d_in[0];
    const int*   ei     = (const int*)  d_in[1];
    const float* Wrel1  = (const float*)d_in[2];
    const float* brel1  = (const float*)d_in[3];
    const float* Wroot1 = (const float*)d_in[4];
    const float* Wrel2  = (const float*)d_in[5];
    const float* brel2  = (const float*)d_in[6];
    const float* Wroot2 = (const float*)d_in[7];
    const float* Wlin   = (const float*)d_in[8];
    const float* blin   = (const float*)d_in[9];
    float* out = (float*)d_out;

    const int nblk = (NN + 511) / 512;   // 196

    // CSR build (reused by both layers)
    zero_cnt_k<<<(NN + 255) / 256, 256>>>();
    hist_k<<<(EE + 255) / 256, 256>>>(ei);
    scan1_k<<<nblk, 512>>>();
    scan2_k<<<1, 256>>>(nblk);
    scan3_k<<<(NN + 255) / 256, 256>>>();
    fill_k<<<(EE + 255) / 256, 256>>>(ei);

    // fp16 copy of x for gather
    cvt_half_k<<<(NN * HH / 4 + 255) / 256, 256>>>(x);

    // layer 1
    agg_h_k<<<NN, 128>>>(1);
    gemm_dual_tf32_k<<<(NN + 127) / 128, 256>>>(x, Wrel1, Wroot1, brel1, 1);

    // layer 2
    agg_h_k<<<NN, 128>>>(2);
    gemm_dual_tf32_k<<<(NN + 127) / 128, 256>>>(x, Wrel2, Wroot2, brel2, 2);

    // head: logits + log_softmax fused
    gemm_logits_tf32_k<<<(NN + 255) / 256, 256>>>(Wlin, blin, out);
}

// round 5
// speedup vs baseline: 2.3244x; 1.3375x over previous
#include <cuda_runtime.h>
#include <cuda_fp16.h>
#include <math.h>
#include <stdint.h>

#define NN 100000
#define EE 1600000
#define HH 128
#define CC 40

// ---- scratch (device globals; no allocation allowed) ----
__device__ __half g_aggh[(size_t)NN * HH];
__device__ __half g_xh  [(size_t)NN * HH];
__device__ __half g_x1h [(size_t)NN * HH];
__device__ __half g_x2h [(size_t)NN * HH];
__device__ int    g_cnt[NN];
__device__ int    g_off[NN + 1];
__device__ int    g_cur[NN];
__device__ int    g_srcs[EE];
__device__ int    g_bsum[256];

// ---------------- CSR build ----------------
__global__ void zero_cnt_k() {
    int i = blockIdx.x * blockDim.x + threadIdx.x;
    if (i < NN) g_cnt[i] = 0;
}

__global__ void hist_k(const int* __restrict__ ei) {
    int e = blockIdx.x * blockDim.x + threadIdx.x;
    if (e < EE) atomicAdd(&g_cnt[ei[EE + e]], 1);
}

__global__ __launch_bounds__(512) void scan1_k() {
    __shared__ int wsum[16];
    const int t = threadIdx.x, lane = t & 31, wid = t >> 5;
    const int i = blockIdx.x * 512 + t;
    int v = (i < NN) ? g_cnt[i] : 0;
    int x = v;
    #pragma unroll
    for (int d = 1; d < 32; d <<= 1) {
        int y = __shfl_up_sync(0xffffffffu, x, d);
        if (lane >= d) x += y;
    }
    if (lane == 31) wsum[wid] = x;
    __syncthreads();
    if (wid == 0 && lane < 16) {
        int w = wsum[lane];
        #pragma unroll
        for (int d = 1; d < 16; d <<= 1) {
            int y = __shfl_up_sync(0xffffu, w, d);
            if (lane >= d) w += y;
        }
        wsum[lane] = w;
    }
    __syncthreads();
    int incl = x + (wid ? wsum[wid - 1] : 0);
    if (i < NN) g_off[i] = incl - v;
    if (t == 511) g_bsum[blockIdx.x] = incl;
}

__global__ __launch_bounds__(256) void scan2_k(int nblk) {
    __shared__ int wsum[8];
    const int t = threadIdx.x, lane = t & 31, wid = t >> 5;
    int v = (t < nblk) ? g_bsum[t] : 0;
    int x = v;
    #pragma unroll
    for (int d = 1; d < 32; d <<= 1) {
        int y = __shfl_up_sync(0xffffffffu, x, d);
        if (lane >= d) x += y;
    }
    if (lane == 31) wsum[wid] = x;
    __syncthreads();
    if (wid == 0 && lane < 8) {
        int w = wsum[lane];
        #pragma unroll
        for (int d = 1; d < 8; d <<= 1) {
            int y = __shfl_up_sync(0xffu, w, d);
            if (lane >= d) w += y;
        }
        wsum[lane] = w;
    }
    __syncthreads();
    int incl = x + (wid ? wsum[wid - 1] : 0);
    if (t < nblk) g_bsum[t] = incl - v;
}

__global__ void scan3_k() {
    int i = blockIdx.x * blockDim.x + threadIdx.x;
    if (i < NN) {
        int o = g_off[i] + g_bsum[i >> 9];
        g_off[i] = o;
        g_cur[i] = o;
    }
    if (i == 0) g_off[NN] = EE;
}

__global__ void fill_k(const int* __restrict__ ei) {
    int e = blockIdx.x * blockDim.x + threadIdx.x;
    if (e < EE) {
        int src = ei[e];
        int dst = ei[EE + e];
        int pos = atomicAdd(&g_cur[dst], 1);
        g_srcs[pos] = src;
    }
}

// ---------------- fp32 -> fp16 convert of input x ----------------
__global__ void cvt_half_k(const float* __restrict__ x) {
    int i = blockIdx.x * blockDim.x + threadIdx.x;
    if (i < NN * HH / 4) {
        float4 v = *(const float4*)(x + (size_t)i * 4);
        __half2* o = (__half2*)(g_xh + (size_t)i * 4);
        o[0] = __floats2half2_rn(v.x, v.y);
        o[1] = __floats2half2_rn(v.z, v.w);
    }
}

// ---------------- edge aggregation: warp per node, fp16 in, fp16 out ----------------
__global__ __launch_bounds__(128) void agg_h_k(int layer) {
    const __half* __restrict__ in = (layer == 1) ? g_xh : g_x1h;
    const int node = blockIdx.x * 4 + (threadIdx.x >> 5);
    if (node >= NN) return;
    const int lane = threadIdx.x & 31;
    const int s = g_off[node], e = g_off[node + 1];
    float a0 = 0.f, a1 = 0.f, a2 = 0.f, a3 = 0.f;
    int p = s;
    for (; p + 1 < e; p += 2) {
        int s0 = g_srcs[p];
        int s1 = g_srcs[p + 1];
        uint2 u0 = *(const uint2*)(in + (size_t)s0 * HH + lane * 4);
        uint2 u1 = *(const uint2*)(in + (size_t)s1 * HH + lane * 4);
        float2 f;
        f = __half22float2(*(__half2*)&u0.x); a0 += f.x; a1 += f.y;
        f = __half22float2(*(__half2*)&u0.y); a2 += f.x; a3 += f.y;
        f = __half22float2(*(__half2*)&u1.x); a0 += f.x; a1 += f.y;
        f = __half22float2(*(__half2*)&u1.y); a2 += f.x; a3 += f.y;
    }
    if (p < e) {
        uint2 u0 = *(const uint2*)(in + (size_t)g_srcs[p] * HH + lane * 4);
        float2 f;
        f = __half22float2(*(__half2*)&u0.x); a0 += f.x; a1 += f.y;
        f = __half22float2(*(__half2*)&u0.y); a2 += f.x; a3 += f.y;
    }
    uint2 o;
    *(__half2*)&o.x = __floats2half2_rn(a0, a1);
    *(__half2*)&o.y = __floats2half2_rn(a2, a3);
    *(uint2*)(g_aggh + (size_t)node * HH + lane * 4) = o;
}

// ---------------- fp16 MMA helpers ----------------
__device__ __forceinline__ void mma_f16(float* d, const uint32_t* a, const uint32_t* b) {
    asm volatile(
        "mma.sync.aligned.m16n8k16.row.col.f32.f16.f16.f32 "
        "{%0,%1,%2,%3}, {%4,%5,%6,%7}, {%8,%9}, {%0,%1,%2,%3};\n"
        : "+f"(d[0]), "+f"(d[1]), "+f"(d[2]), "+f"(d[3])
        : "r"(a[0]), "r"(a[1]), "r"(a[2]), "r"(a[3]),
          "r"(b[0]), "r"(b[1]));
}

__device__ __forceinline__ void ldsm_x4(uint32_t& r0, uint32_t& r1, uint32_t& r2, uint32_t& r3, uint32_t addr) {
    asm volatile("ldmatrix.sync.aligned.m8n8.x4.shared.b16 {%0,%1,%2,%3}, [%4];"
                 : "=r"(r0), "=r"(r1), "=r"(r2), "=r"(r3) : "r"(addr));
}

__device__ __forceinline__ void ldsm_x4_t(uint32_t& r0, uint32_t& r1, uint32_t& r2, uint32_t& r3, uint32_t addr) {
    asm volatile("ldmatrix.sync.aligned.m8n8.x4.trans.shared.b16 {%0,%1,%2,%3}, [%4];"
                 : "=r"(r0), "=r"(r1), "=r"(r2), "=r"(r3) : "r"(addr));
}

__device__ __forceinline__ void ldsm_x2_t(uint32_t& r0, uint32_t& r1, uint32_t addr) {
    asm volatile("ldmatrix.sync.aligned.m8n8.x2.trans.shared.b16 {%0,%1}, [%2];"
                 : "=r"(r0), "=r"(r1) : "r"(addr));
}

// ---------------- fused dual GEMM (fp16 MMA) ----------------
// C = relu([agg | src] @ [Brel ; Broot] + bias) -> half, M=NN, N=128, K=256
// BM=128, BN=128, BK=32, 8 warps (2x4), warp tile 64x32
#define SA_STRIDE 40   // halfs; 80B rows -> conflict-free LDSM
#define SB_STRIDE 136  // halfs; 272B rows -> conflict-free LDSM
__global__ __launch_bounds__(256) void gemm_dual_f16_k(
    const __half* __restrict__ A2h,
    const float* __restrict__ B1, const float* __restrict__ B2,
    const float* __restrict__ bias, __half* __restrict__ Ch)
{
    __shared__ __half sA[128 * SA_STRIDE];
    __shared__ __half sB[32 * SB_STRIDE];

    const int t    = threadIdx.x;
    const int lane = t & 31;
    const int wid  = t >> 5;
    const int wm   = wid >> 2;
    const int wn   = wid & 3;
    const int m0   = blockIdx.x * 128;

    const uint32_t sa_base = (uint32_t)__cvta_generic_to_shared(sA);
    const uint32_t sb_base = (uint32_t)__cvta_generic_to_shared(sB);

    float acc[4][4][4];
    #pragma unroll
    for (int mt = 0; mt < 4; mt++)
        #pragma unroll
        for (int nt = 0; nt < 4; nt++)
            #pragma unroll
            for (int q = 0; q < 4; q++) acc[mt][nt][q] = 0.f;

    // ldmatrix lane address components
    const int li  = lane >> 3;          // matrix id 0..3
    const int lr  = lane & 7;
    const int a_row = (li & 1) * 8 + lr;
    const int a_kof = (li >> 1) * 8;
    const int b_krow = (li & 1) * 8 + lr;
    const int b_nof  = (li >> 1) * 8;

    #pragma unroll 1
    for (int s = 0; s < 8; ++s) {
        const __half* __restrict__ Asrc = (s < 4) ? g_aggh : A2h;
        const float*  __restrict__ Bsrc = (s < 4) ? B1 : B2;
        const int kb = (s & 3) * 32;

        // stage A: 128 rows x 32 halfs = 512 uint4; 2 uint4 per thread
        // row r needs 4 uint4 at half-offsets {0,8,16,24}: r = idx>>2, c = (idx&3)*8
        #pragma unroll
        for (int q = 0; q < 2; ++q) {
            int idx = q * 256 + t;       // 0..511
            int r   = idx >> 2;          // 0..127
            int c   = (idx & 3) * 8;     // 0,8,16,24
            int grow = m0 + r;
            uint4 v = (grow < NN)
                ? *(const uint4*)(Asrc + (size_t)grow * HH + kb + c)
                : make_uint4(0u, 0u, 0u, 0u);
            *(uint4*)&sA[r * SA_STRIDE + c] = v;
        }
        // stage B: 32x128 fp32 -> halfs (1024 float4, 4 per thread)
        #pragma unroll
        for (int q = 0; q < 4; ++q) {
            int idx = q * 256 + t;       // 0..1023
            int kr  = idx >> 5;          // 0..31
            int c4  = (idx & 31) * 4;    // 0..124
            float4 v = *(const float4*)(Bsrc + (size_t)(kb + kr) * 128 + c4);
            uint2 h;
            *(__half2*)&h.x = __floats2half2_rn(v.x, v.y);
            *(__half2*)&h.y = __floats2half2_rn(v.z, v.w);
            *(uint2*)&sB[kr * SB_STRIDE + c4] = h;
        }
        __syncthreads();

        #pragma unroll
        for (int kk = 0; kk < 2; ++kk) {
            const int k0 = kk * 16;
            uint32_t a[4][4], b[4][2];
            #pragma unroll
            for (int mt = 0; mt < 4; ++mt) {
                uint32_t addr = sa_base +
                    ((wm * 64 + mt * 16 + a_row) * SA_STRIDE + k0 + a_kof) * 2;
                ldsm_x4(a[mt][0], a[mt][1], a[mt][2], a[mt][3], addr);
            }
            #pragma unroll
            for (int p = 0; p < 2; ++p) {
                uint32_t addr = sb_base +
                    ((k0 + b_krow) * SB_STRIDE + wn * 32 + p * 16 + b_nof) * 2;
                ldsm_x4_t(b[2 * p][0], b[2 * p][1], b[2 * p + 1][0], b[2 * p + 1][1], addr);
            }
            #pragma unroll
            for (int mt = 0; mt < 4; ++mt)
                #pragma unroll
                for (int nt = 0; nt < 4; ++nt)
                    mma_f16(acc[mt][nt], a[mt], b[nt]);
        }
        __syncthreads();
    }

    // epilogue: bias + relu -> half
    const int r0 = m0 + wm * 64 + (lane >> 2);
    const int c0 = wn * 32 + 2 * (lane & 3);
    #pragma unroll
    for (int nt = 0; nt < 4; ++nt) {
        int col = c0 + nt * 8;
        float bb0 = bias[col], bb1 = bias[col + 1];
        #pragma unroll
        for (int mt = 0; mt < 4; ++mt) {
            int row = r0 + mt * 16;
            if (row < NN) {
                float v0 = fmaxf(acc[mt][nt][0] + bb0, 0.f);
                float v1 = fmaxf(acc[mt][nt][1] + bb1, 0.f);
                *(__half2*)&Ch[(size_t)row * HH + col] = __floats2half2_rn(v0, v1);
            }
            if (row + 8 < NN) {
                float v2 = fmaxf(acc[mt][nt][2] + bb0, 0.f);
                float v3 = fmaxf(acc[mt][nt][3] + bb1, 0.f);
                *(__half2*)&Ch[(size_t)(row + 8) * HH + col] = __floats2half2_rn(v2, v3);
            }
        }
    }
}

// ---------------- logits GEMM (fp16 MMA) + fused log_softmax ----------------
// out = log_softmax([x1|x2] @ W_lin + b_lin), M=NN, N=40, K=256
#define LB_STRIDE 40
__global__ __launch_bounds__(256) void gemm_logits_f16_k(
    const float* __restrict__ W, const float* __restrict__ bias,
    float* __restrict__ out)
{
    __shared__ __half sA[256 * SA_STRIDE];
    __shared__ __half sB[32 * LB_STRIDE];

    const int t    = threadIdx.x;
    const int lane = t & 31;
    const int w    = t >> 5;
    const int m0   = blockIdx.x * 256;

    const uint32_t sa_base = (uint32_t)__cvta_generic_to_shared(sA);
    const uint32_t sb_base = (uint32_t)__cvta_generic_to_shared(sB);

    float acc[2][5][4];
    #pragma unroll
    for (int mt = 0; mt < 2; mt++)
        #pragma unroll
        for (int nt = 0; nt < 5; nt++)
            #pragma unroll
            for (int q = 0; q < 4; q++) acc[mt][nt][q] = 0.f;

    const int li  = lane >> 3;
    const int lr  = lane & 7;
    const int a_row = (li & 1) * 8 + lr;
    const int a_kof = (li >> 1) * 8;
    const int b_krow = ((lane >> 3) & 1) * 8 + lr;   // x2.trans uses lanes 0-15

    #pragma unroll 1
    for (int k0g = 0; k0g < 256; k0g += 32) {
        const __half* __restrict__ A = (k0g < 128) ? g_x1h : g_x2h;
        const int kb = k0g & 127;
        // stage A: 256 rows x 32 halfs = 1024 uint4; 4 per thread
        #pragma unroll
        for (int q = 0; q < 4; ++q) {
            int idx = q * 256 + t;       // 0..1023
            int r   = idx >> 2;          // 0..255
            int c   = (idx & 3) * 8;     // 0,8,16,24
            int grow = m0 + r;
            uint4 v = (grow < NN)
                ? *(const uint4*)(A + (size_t)grow * HH + kb + c)
                : make_uint4(0u, 0u, 0u, 0u);
            *(uint4*)&sA[r * SA_STRIDE + c] = v;
        }
        // stage B: 32x40 fp32 -> halfs (640 half2)
        #pragma unroll
        for (int q = 0; q < 3; ++q) {
            int idx = q * 256 + t;
            if (idx < 640) {
                int kr = idx / 20, c2 = (idx % 20) * 2;
                float2 v = *(const float2*)(W + (size_t)(k0g + kr) * 40 + c2);
                *(__half2*)&sB[kr * LB_STRIDE + c2] = __floats2half2_rn(v.x, v.y);
            }
        }
        __syncthreads();

        #pragma unroll
        for (int kk = 0; kk < 2; ++kk) {
            const int k0 = kk * 16;
            uint32_t a[2][4], b[5][2];
            #pragma unroll
            for (int mt = 0; mt < 2; ++mt) {
                uint32_t addr = sa_base +
                    ((w * 32 + mt * 16 + a_row) * SA_STRIDE + k0 + a_kof) * 2;
                ldsm_x4(a[mt][0], a[mt][1], a[mt][2], a[mt][3], addr);
            }
            #pragma unroll
            for (int nt = 0; nt < 5; ++nt) {
                uint32_t addr = sb_base +
                    ((k0 + b_krow) * LB_STRIDE + nt * 8) * 2;
                ldsm_x2_t(b[nt][0], b[nt][1], addr);
            }
            #pragma unroll
            for (int mt = 0; mt < 2; ++mt)
                #pragma unroll
                for (int nt = 0; nt < 5; ++nt)
                    mma_f16(acc[mt][nt], a[mt], b[nt]);
        }
        __syncthreads();
    }

    // fused epilogue: bias + log_softmax per row
    #pragma unroll
    for (int mt = 0; mt < 2; ++mt) {
        float vA[10], vB[10];
        #pragma unroll
        for (int nt = 0; nt < 5; ++nt) {
            #pragma unroll
            for (int j = 0; j < 2; ++j) {
                int c = nt * 8 + 2 * (lane & 3) + j;
                float bb = bias[c];
                vA[nt * 2 + j] = acc[mt][nt][j]     + bb;
                vB[nt * 2 + j] = acc[mt][nt][2 + j] + bb;
            }
        }
        float mA = vA[0], mB = vB[0];
        #pragma unroll
        for (int k = 1; k < 10; ++k) { mA = fmaxf(mA, vA[k]); mB = fmaxf(mB, vB[k]); }
        mA = fmaxf(mA, __shfl_xor_sync(0xffffffffu, mA, 1));
        mA = fmaxf(mA, __shfl_xor_sync(0xffffffffu, mA, 2));
        mB = fmaxf(mB, __shfl_xor_sync(0xffffffffu, mB, 1));
        mB = fmaxf(mB, __shfl_xor_sync(0xffffffffu, mB, 2));
        float eA = 0.f, eB = 0.f;
        #pragma unroll
        for (int k = 0; k < 10; ++k) { eA += expf(vA[k] - mA); eB += expf(vB[k] - mB); }
        eA += __shfl_xor_sync(0xffffffffu, eA, 1);
        eA += __shfl_xor_sync(0xffffffffu, eA, 2);
        eB += __shfl_xor_sync(0xffffffffu, eB, 1);
        eB += __shfl_xor_sync(0xffffffffu, eB, 2);
        float lA = mA + logf(eA), lB = mB + logf(eB);

        int rowA = m0 + w * 32 + mt * 16 + (lane >> 2);
        int rowB = rowA + 8;
        #pragma unroll
        for (int nt = 0; nt < 5; ++nt) {
            int c = nt * 8 + 2 * (lane & 3);
            if (rowA < NN)
                *(float2*)&out[(size_t)rowA * 40 + c] =
                    make_float2(vA[nt * 2] - lA, vA[nt * 2 + 1] - lA);
            if (rowB < NN)
                *(float2*)&out[(size_t)rowB * 40 + c] =
                    make_float2(vB[nt * 2] - lB, vB[nt * 2 + 1] - lB);
        }
    }
}

// ---------------- launch ----------------
extern "C" void kernel_launch(void* const* d_in, const int* in_sizes, int n_in,
                              void* d_out, int out_size) {
    const float* x      = (const float*)d_in[0];
    const int*   ei     = (const int*)  d_in[1];
    const float* Wrel1  = (const float*)d_in[2];
    const float* brel1  = (const float*)d_in[3];
    const float* Wroot1 = (const float*)d_in[4];
    const float* Wrel2  = (const float*)d_in[5];
    const float* brel2  = (const float*)d_in[6];
    const float* Wroot2 = (const float*)d_in[7];
    const float* Wlin   = (const float*)d_in[8];
    const float* blin   = (const float*)d_in[9];
    float* out = (float*)d_out;

    const int nblk = (NN + 511) / 512;

    __half* xh;  cudaGetSymbolAddress((void**)&xh,  g_xh);
    __half* x1h; cudaGetSymbolAddress((void**)&x1h, g_x1h);
    __half* x2h; cudaGetSymbolAddress((void**)&x2h, g_x2h);

    // CSR build (reused by both layers)
    zero_cnt_k<<<(NN + 255) / 256, 256>>>();
    hist_k<<<(EE + 255) / 256, 256>>>(ei);
    scan1_k<<<nblk, 512>>>();
    scan2_k<<<1, 256>>>(nblk);
    scan3_k<<<(NN + 255) / 256, 256>>>();
    fill_k<<<(EE + 255) / 256, 256>>>(ei);

    // fp16 copy of x
    cvt_half_k<<<(NN * HH / 4 + 255) / 256, 256>>>(x);

    // layer 1
    agg_h_k<<<(NN + 3) / 4, 128>>>(1);
    gemm_dual_f16_k<<<(NN + 127) / 128, 256>>>(xh, Wrel1, Wroot1, brel1, x1h);

    // layer 2
    agg_h_k<<<(NN + 3) / 4, 128>>>(2);
    gemm_dual_f16_k<<<(NN + 127) / 128, 256>>>(x1h, Wrel2, Wroot2, brel2, x2h);

    // head: logits + log_softmax fused
    gemm_logits_f16_k<<<(NN + 255) / 256, 256>>>(Wlin, blin, out);
}

// round 6
// speedup vs baseline: 3.2287x; 1.3890x over previous
#include <cuda_runtime.h>
#include <cuda_fp16.h>
#include <math.h>
#include <stdint.h>

#define NN 100000
#define EE 1600000
#define HH 128
#define CC 40

// ---- scratch (device globals; no allocation allowed) ----
__device__ __half g_yh  [(size_t)NN * HH];   // x @ W_rel   (per layer, reused)
__device__ __half g_rh  [(size_t)NN * HH];   // x @ W_root  (per layer, reused)
__device__ __half g_x1h [(size_t)NN * HH];
__device__ __half g_x2h [(size_t)NN * HH];
__device__ int    g_cnt[NN];
__device__ int    g_off[NN + 1];
__device__ int    g_cur[NN];
__device__ int    g_srcs[EE];
__device__ int    g_bsum[256];

// ---------------- CSR build ----------------
__global__ void zero_cnt_k() {
    int i = blockIdx.x * blockDim.x + threadIdx.x;
    if (i < NN) g_cnt[i] = 0;
}

__global__ void hist_k(const int* __restrict__ ei) {
    int e = blockIdx.x * blockDim.x + threadIdx.x;
    if (e < EE) atomicAdd(&g_cnt[ei[EE + e]], 1);
}

__global__ __launch_bounds__(512) void scan1_k() {
    __shared__ int wsum[16];
    const int t = threadIdx.x, lane = t & 31, wid = t >> 5;
    const int i = blockIdx.x * 512 + t;
    int v = (i < NN) ? g_cnt[i] : 0;
    int x = v;
    #pragma unroll
    for (int d = 1; d < 32; d <<= 1) {
        int y = __shfl_up_sync(0xffffffffu, x, d);
        if (lane >= d) x += y;
    }
    if (lane == 31) wsum[wid] = x;
    __syncthreads();
    if (wid == 0 && lane < 16) {
        int w = wsum[lane];
        #pragma unroll
        for (int d = 1; d < 16; d <<= 1) {
            int y = __shfl_up_sync(0xffffu, w, d);
            if (lane >= d) w += y;
        }
        wsum[lane] = w;
    }
    __syncthreads();
    int incl = x + (wid ? wsum[wid - 1] : 0);
    if (i < NN) g_off[i] = incl - v;
    if (t == 511) g_bsum[blockIdx.x] = incl;
}

__global__ __launch_bounds__(256) void scan2_k(int nblk) {
    __shared__ int wsum[8];
    const int t = threadIdx.x, lane = t & 31, wid = t >> 5;
    int v = (t < nblk) ? g_bsum[t] : 0;
    int x = v;
    #pragma unroll
    for (int d = 1; d < 32; d <<= 1) {
        int y = __shfl_up_sync(0xffffffffu, x, d);
        if (lane >= d) x += y;
    }
    if (lane == 31) wsum[wid] = x;
    __syncthreads();
    if (wid == 0 && lane < 8) {
        int w = wsum[lane];
        #pragma unroll
        for (int d = 1; d < 8; d <<= 1) {
            int y = __shfl_up_sync(0xffu, w, d);
            if (lane >= d) w += y;
        }
        wsum[lane] = w;
    }
    __syncthreads();
    int incl = x + (wid ? wsum[wid - 1] : 0);
    if (t < nblk) g_bsum[t] = incl - v;
}

__global__ void scan3_k() {
    int i = blockIdx.x * blockDim.x + threadIdx.x;
    if (i < NN) {
        int o = g_off[i] + g_bsum[i >> 9];
        g_off[i] = o;
        g_cur[i] = o;
    }
    if (i == 0) g_off[NN] = EE;
}

__global__ void fill_k(const int* __restrict__ ei) {
    int e = blockIdx.x * blockDim.x + threadIdx.x;
    if (e < EE) {
        int src = ei[e];
        int dst = ei[EE + e];
        int pos = atomicAdd(&g_cur[dst], 1);
        g_srcs[pos] = src;
    }
}

// ---------------- fused aggregation: xo = relu(segsum(y[src]) + r + bias) ----------------
// warp per node, lane owns 4 consecutive cols
__global__ __launch_bounds__(128) void agg_fused_k(
    const __half* __restrict__ y, const __half* __restrict__ r,
    const float* __restrict__ bias, __half* __restrict__ xo)
{
    const int node = blockIdx.x * 4 + (threadIdx.x >> 5);
    if (node >= NN) return;
    const int lane = threadIdx.x & 31;
    const int s = g_off[node], e = g_off[node + 1];
    float a0 = 0.f, a1 = 0.f, a2 = 0.f, a3 = 0.f;
    int p = s;
    for (; p + 1 < e; p += 2) {
        int s0 = g_srcs[p];
        int s1 = g_srcs[p + 1];
        uint2 u0 = *(const uint2*)(y + (size_t)s0 * HH + lane * 4);
        uint2 u1 = *(const uint2*)(y + (size_t)s1 * HH + lane * 4);
        float2 f;
        f = __half22float2(*(__half2*)&u0.x); a0 += f.x; a1 += f.y;
        f = __half22float2(*(__half2*)&u0.y); a2 += f.x; a3 += f.y;
        f = __half22float2(*(__half2*)&u1.x); a0 += f.x; a1 += f.y;
        f = __half22float2(*(__half2*)&u1.y); a2 += f.x; a3 += f.y;
    }
    if (p < e) {
        uint2 u0 = *(const uint2*)(y + (size_t)g_srcs[p] * HH + lane * 4);
        float2 f;
        f = __half22float2(*(__half2*)&u0.x); a0 += f.x; a1 += f.y;
        f = __half22float2(*(__half2*)&u0.y); a2 += f.x; a3 += f.y;
    }
    // root + bias + relu
    uint2 rv = *(const uint2*)(r + (size_t)node * HH + lane * 4);
    float4 bb = *(const float4*)(bias + lane * 4);
    float2 f;
    f = __half22float2(*(__half2*)&rv.x);
    a0 = fmaxf(a0 + f.x + bb.x, 0.f);
    a1 = fmaxf(a1 + f.y + bb.y, 0.f);
    f = __half22float2(*(__half2*)&rv.y);
    a2 = fmaxf(a2 + f.x + bb.z, 0.f);
    a3 = fmaxf(a3 + f.y + bb.w, 0.f);
    uint2 o;
    *(__half2*)&o.x = __floats2half2_rn(a0, a1);
    *(__half2*)&o.y = __floats2half2_rn(a2, a3);
    *(uint2*)(xo + (size_t)node * HH + lane * 4) = o;
}

// ---------------- fp16 MMA helpers ----------------
__device__ __forceinline__ void mma_f16(float* d, const uint32_t* a, const uint32_t* b) {
    asm volatile(
        "mma.sync.aligned.m16n8k16.row.col.f32.f16.f16.f32 "
        "{%0,%1,%2,%3}, {%4,%5,%6,%7}, {%8,%9}, {%0,%1,%2,%3};\n"
        : "+f"(d[0]), "+f"(d[1]), "+f"(d[2]), "+f"(d[3])
        : "r"(a[0]), "r"(a[1]), "r"(a[2]), "r"(a[3]),
          "r"(b[0]), "r"(b[1]));
}

__device__ __forceinline__ void ldsm_x4(uint32_t& r0, uint32_t& r1, uint32_t& r2, uint32_t& r3, uint32_t addr) {
    asm volatile("ldmatrix.sync.aligned.m8n8.x4.shared.b16 {%0,%1,%2,%3}, [%4];"
                 : "=r"(r0), "=r"(r1), "=r"(r2), "=r"(r3) : "r"(addr));
}

__device__ __forceinline__ void ldsm_x4_t(uint32_t& r0, uint32_t& r1, uint32_t& r2, uint32_t& r3, uint32_t addr) {
    asm volatile("ldmatrix.sync.aligned.m8n8.x4.trans.shared.b16 {%0,%1,%2,%3}, [%4];"
                 : "=r"(r0), "=r"(r1), "=r"(r2), "=r"(r3) : "r"(addr));
}

__device__ __forceinline__ void ldsm_x2_t(uint32_t& r0, uint32_t& r1, uint32_t addr) {
    asm volatile("ldmatrix.sync.aligned.m8n8.x2.trans.shared.b16 {%0,%1}, [%2];"
                 : "=r"(r0), "=r"(r1) : "r"(addr));
}

// ---------------- layer GEMM: C = A @ B (half out), M=NN, N=128, K=128 ----------------
// grid.y selects (B1 -> C1) or (B2 -> C2). A is fp32 (layer 1) or half (layer 2).
// BM=128, BK=32, 8 warps (2x4), warp tile 64x32
#define SA_STRIDE 40   // halfs; 80B rows -> conflict-free LDSM
#define SB_STRIDE 136  // halfs; 272B rows -> conflict-free LDSM
__global__ __launch_bounds__(256) void gemm_xw_k(
    const float* __restrict__ Af, const __half* __restrict__ Ah, int a_is_f32,
    const float* __restrict__ B1, const float* __restrict__ B2,
    __half* __restrict__ C1, __half* __restrict__ C2)
{
    const float* __restrict__ B = blockIdx.y ? B2 : B1;
    __half* __restrict__ C = blockIdx.y ? C2 : C1;

    __shared__ __half sA[128 * SA_STRIDE];
    __shared__ __half sB[32 * SB_STRIDE];

    const int t    = threadIdx.x;
    const int lane = t & 31;
    const int wid  = t >> 5;
    const int wm   = wid >> 2;
    const int wn   = wid & 3;
    const int m0   = blockIdx.x * 128;

    const uint32_t sa_base = (uint32_t)__cvta_generic_to_shared(sA);
    const uint32_t sb_base = (uint32_t)__cvta_generic_to_shared(sB);

    float acc[4][4][4];
    #pragma unroll
    for (int mt = 0; mt < 4; mt++)
        #pragma unroll
        for (int nt = 0; nt < 4; nt++)
            #pragma unroll
            for (int q = 0; q < 4; q++) acc[mt][nt][q] = 0.f;

    const int li  = lane >> 3;
    const int lr  = lane & 7;
    const int a_row = (li & 1) * 8 + lr;
    const int a_kof = (li >> 1) * 8;
    const int b_krow = (li & 1) * 8 + lr;
    const int b_nof  = (li >> 1) * 8;

    #pragma unroll 1
    for (int s = 0; s < 4; ++s) {
        const int kb = s * 32;

        if (a_is_f32) {
            // 128 rows x 32 floats = 1024 float4; 4 per thread -> half
            #pragma unroll
            for (int q = 0; q < 4; ++q) {
                int idx = q * 256 + t;
                int r   = idx >> 3;          // 0..127
                int c4  = (idx & 7) * 4;     // 0..28
                int grow = m0 + r;
                float4 v = (grow < NN)
                    ? *(const float4*)(Af + (size_t)grow * HH + kb + c4)
                    : make_float4(0.f, 0.f, 0.f, 0.f);
                uint2 h;
                *(__half2*)&h.x = __floats2half2_rn(v.x, v.y);
                *(__half2*)&h.y = __floats2half2_rn(v.z, v.w);
                *(uint2*)&sA[r * SA_STRIDE + c4] = h;
            }
        } else {
            // 128 rows x 32 halfs = 512 uint4; 2 per thread
            #pragma unroll
            for (int q = 0; q < 2; ++q) {
                int idx = q * 256 + t;
                int r   = idx >> 2;          // 0..127
                int c   = (idx & 3) * 8;     // 0,8,16,24
                int grow = m0 + r;
                uint4 v = (grow < NN)
                    ? *(const uint4*)(Ah + (size_t)grow * HH + kb + c)
                    : make_uint4(0u, 0u, 0u, 0u);
                *(uint4*)&sA[r * SA_STRIDE + c] = v;
            }
        }
        // stage B: 32x128 fp32 -> halfs
        #pragma unroll
        for (int q = 0; q < 4; ++q) {
            int idx = q * 256 + t;
            int kr  = idx >> 5;
            int c4  = (idx & 31) * 4;
            float4 v = *(const float4*)(B + (size_t)(kb + kr) * 128 + c4);
            uint2 h;
            *(__half2*)&h.x = __floats2half2_rn(v.x, v.y);
            *(__half2*)&h.y = __floats2half2_rn(v.z, v.w);
            *(uint2*)&sB[kr * SB_STRIDE + c4] = h;
        }
        __syncthreads();

        #pragma unroll
        for (int kk = 0; kk < 2; ++kk) {
            const int k0 = kk * 16;
            uint32_t a[4][4], b[4][2];
            #pragma unroll
            for (int mt = 0; mt < 4; ++mt) {
                uint32_t addr = sa_base +
                    ((wm * 64 + mt * 16 + a_row) * SA_STRIDE + k0 + a_kof) * 2;
                ldsm_x4(a[mt][0], a[mt][1], a[mt][2], a[mt][3], addr);
            }
            #pragma unroll
            for (int p = 0; p < 2; ++p) {
                uint32_t addr = sb_base +
                    ((k0 + b_krow) * SB_STRIDE + wn * 32 + p * 16 + b_nof) * 2;
                ldsm_x4_t(b[2 * p][0], b[2 * p][1], b[2 * p + 1][0], b[2 * p + 1][1], addr);
            }
            #pragma unroll
            for (int mt = 0; mt < 4; ++mt)
                #pragma unroll
                for (int nt = 0; nt < 4; ++nt)
                    mma_f16(acc[mt][nt], a[mt], b[nt]);
        }
        __syncthreads();
    }

    // epilogue: plain half stores
    const int r0 = m0 + wm * 64 + (lane >> 2);
    const int c0 = wn * 32 + 2 * (lane & 3);
    #pragma unroll
    for (int nt = 0; nt < 4; ++nt) {
        int col = c0 + nt * 8;
        #pragma unroll
        for (int mt = 0; mt < 4; ++mt) {
            int row = r0 + mt * 16;
            if (row < NN)
                *(__half2*)&C[(size_t)row * HH + col] =
                    __floats2half2_rn(acc[mt][nt][0], acc[mt][nt][1]);
            if (row + 8 < NN)
                *(__half2*)&C[(size_t)(row + 8) * HH + col] =
                    __floats2half2_rn(acc[mt][nt][2], acc[mt][nt][3]);
        }
    }
}

// ---------------- logits GEMM (fp16 MMA) + fused log_softmax ----------------
#define LB_STRIDE 40
__global__ __launch_bounds__(256) void gemm_logits_f16_k(
    const float* __restrict__ W, const float* __restrict__ bias,
    float* __restrict__ out)
{
    __shared__ __half sA[256 * SA_STRIDE];
    __shared__ __half sB[32 * LB_STRIDE];

    const int t    = threadIdx.x;
    const int lane = t & 31;
    const int w    = t >> 5;
    const int m0   = blockIdx.x * 256;

    const uint32_t sa_base = (uint32_t)__cvta_generic_to_shared(sA);
    const uint32_t sb_base = (uint32_t)__cvta_generic_to_shared(sB);

    float acc[2][5][4];
    #pragma unroll
    for (int mt = 0; mt < 2; mt++)
        #pragma unroll
        for (int nt = 0; nt < 5; nt++)
            #pragma unroll
            for (int q = 0; q < 4; q++) acc[mt][nt][q] = 0.f;

    const int li  = lane >> 3;
    const int lr  = lane & 7;
    const int a_row = (li & 1) * 8 + lr;
    const int a_kof = (li >> 1) * 8;
    const int b_krow = ((lane >> 3) & 1) * 8 + lr;

    #pragma unroll 1
    for (int k0g = 0; k0g < 256; k0g += 32) {
        const __half* __restrict__ A = (k0g < 128) ? g_x1h : g_x2h;
        const int kb = k0g & 127;
        #pragma unroll
        for (int q = 0; q < 4; ++q) {
            int idx = q * 256 + t;
            int r   = idx >> 2;
            int c   = (idx & 3) * 8;
            int grow = m0 + r;
            uint4 v = (grow < NN)
                ? *(const uint4*)(A + (size_t)grow * HH + kb + c)
                : make_uint4(0u, 0u, 0u, 0u);
            *(uint4*)&sA[r * SA_STRIDE + c] = v;
        }
        #pragma unroll
        for (int q = 0; q < 3; ++q) {
            int idx = q * 256 + t;
            if (idx < 640) {
                int kr = idx / 20, c2 = (idx % 20) * 2;
                float2 v = *(const float2*)(W + (size_t)(k0g + kr) * 40 + c2);
                *(__half2*)&sB[kr * LB_STRIDE + c2] = __floats2half2_rn(v.x, v.y);
            }
        }
        __syncthreads();

        #pragma unroll
        for (int kk = 0; kk < 2; ++kk) {
            const int k0 = kk * 16;
            uint32_t a[2][4], b[5][2];
            #pragma unroll
            for (int mt = 0; mt < 2; ++mt) {
                uint32_t addr = sa_base +
                    ((w * 32 + mt * 16 + a_row) * SA_STRIDE + k0 + a_kof) * 2;
                ldsm_x4(a[mt][0], a[mt][1], a[mt][2], a[mt][3], addr);
            }
            #pragma unroll
            for (int nt = 0; nt < 5; ++nt) {
                uint32_t addr = sb_base +
                    ((k0 + b_krow) * LB_STRIDE + nt * 8) * 2;
                ldsm_x2_t(b[nt][0], b[nt][1], addr);
            }
            #pragma unroll
            for (int mt = 0; mt < 2; ++mt)
                #pragma unroll
                for (int nt = 0; nt < 5; ++nt)
                    mma_f16(acc[mt][nt], a[mt], b[nt]);
        }
        __syncthreads();
    }

    #pragma unroll
    for (int mt = 0; mt < 2; ++mt) {
        float vA[10], vB[10];
        #pragma unroll
        for (int nt = 0; nt < 5; ++nt) {
            #pragma unroll
            for (int j = 0; j < 2; ++j) {
                int c = nt * 8 + 2 * (lane & 3) + j;
                float bb = bias[c];
                vA[nt * 2 + j] = acc[mt][nt][j]     + bb;
                vB[nt * 2 + j] = acc[mt][nt][2 + j] + bb;
            }
        }
        float mA = vA[0], mB = vB[0];
        #pragma unroll
        for (int k = 1; k < 10; ++k) { mA = fmaxf(mA, vA[k]); mB = fmaxf(mB, vB[k]); }
        mA = fmaxf(mA, __shfl_xor_sync(0xffffffffu, mA, 1));
        mA = fmaxf(mA, __shfl_xor_sync(0xffffffffu, mA, 2));
        mB = fmaxf(mB, __shfl_xor_sync(0xffffffffu, mB, 1));
        mB = fmaxf(mB, __shfl_xor_sync(0xffffffffu, mB, 2));
        float eA = 0.f, eB = 0.f;
        #pragma unroll
        for (int k = 0; k < 10; ++k) { eA += expf(vA[k] - mA); eB += expf(vB[k] - mB); }
        eA += __shfl_xor_sync(0xffffffffu, eA, 1);
        eA += __shfl_xor_sync(0xffffffffu, eA, 2);
        eB += __shfl_xor_sync(0xffffffffu, eB, 1);
        eB += __shfl_xor_sync(0xffffffffu, eB, 2);
        float lA = mA + logf(eA), lB = mB + logf(eB);

        int rowA = m0 + w * 32 + mt * 16 + (lane >> 2);
        int rowB = rowA + 8;
        #pragma unroll
        for (int nt = 0; nt < 5; ++nt) {
            int c = nt * 8 + 2 * (lane & 3);
            if (rowA < NN)
                *(float2*)&out[(size_t)rowA * 40 + c] =
                    make_float2(vA[nt * 2] - lA, vA[nt * 2 + 1] - lA);
            if (rowB < NN)
                *(float2*)&out[(size_t)rowB * 40 + c] =
                    make_float2(vB[nt * 2] - lB, vB[nt * 2 + 1] - lB);
        }
    }
}

// ---------------- launch ----------------
extern "C" void kernel_launch(void* const* d_in, const int* in_sizes, int n_in,
                              void* d_out, int out_size) {
    const float* x      = (const float*)d_in[0];
    const int*   ei     = (const int*)  d_in[1];
    const float* Wrel1  = (const float*)d_in[2];
    const float* brel1  = (const float*)d_in[3];
    const float* Wroot1 = (const float*)d_in[4];
    const float* Wrel2  = (const float*)d_in[5];
    const float* brel2  = (const float*)d_in[6];
    const float* Wroot2 = (const float*)d_in[7];
    const float* Wlin   = (const float*)d_in[8];
    const float* blin   = (const float*)d_in[9];
    float* out = (float*)d_out;

    const int nblk = (NN + 511) / 512;

    __half *yh, *rh, *x1h, *x2h;
    cudaGetSymbolAddress((void**)&yh,  g_yh);
    cudaGetSymbolAddress((void**)&rh,  g_rh);
    cudaGetSymbolAddress((void**)&x1h, g_x1h);
    cudaGetSymbolAddress((void**)&x2h, g_x2h);

    // CSR build (reused by both layers)
    zero_cnt_k<<<(NN + 255) / 256, 256>>>();
    hist_k<<<(EE + 255) / 256, 256>>>(ei);
    scan1_k<<<nblk, 512>>>();
    scan2_k<<<1, 256>>>(nblk);
    scan3_k<<<(NN + 255) / 256, 256>>>();
    fill_k<<<(EE + 255) / 256, 256>>>(ei);

    dim3 ggrid((NN + 127) / 128, 2);

    // layer 1: [y|r] = x @ [Wrel1 | Wroot1], then fused agg
    gemm_xw_k<<<ggrid, 256>>>(x, nullptr, 1, Wrel1, Wroot1, yh, rh);
    agg_fused_k<<<(NN + 3) / 4, 128>>>(yh, rh, brel1, x1h);

    // layer 2
    gemm_xw_k<<<ggrid, 256>>>(nullptr, x1h, 0, Wrel2, Wroot2, yh, rh);
    agg_fused_k<<<(NN + 3) / 4, 128>>>(yh, rh, brel2, x2h);

    // head: logits + log_softmax fused
    gemm_logits_f16_k<<<(NN + 255) / 256, 256>>>(Wlin, blin, out);
}

// round 7
// speedup vs baseline: 3.2943x; 1.0203x over previous
#include <cuda_runtime.h>
#include <cuda_fp16.h>
#include <math.h>
#include <stdint.h>

#define NN 100000
#define EE 1600000
#define HH 128
#define CC 40

// ---- scratch (device globals; no allocation allowed) ----
__device__ __half g_yh  [(size_t)NN * HH];   // x @ W_rel   (per layer, reused)
__device__ __half g_rh  [(size_t)NN * HH];   // x @ W_root  (per layer, reused)
__device__ __half g_x1h [(size_t)NN * HH];
__device__ __half g_x2h [(size_t)NN * HH];
__device__ int    g_cnt[NN];
__device__ int    g_off[NN + 1];
__device__ int    g_cur[NN];
__device__ int    g_srcs[EE];
__device__ int    g_bsum[256];

// ---------------- CSR build ----------------
__global__ void zero_cnt_k() {
    int i = blockIdx.x * blockDim.x + threadIdx.x;
    if (i < NN) g_cnt[i] = 0;
}

__global__ void hist_k(const int* __restrict__ ei) {
    int e = blockIdx.x * blockDim.x + threadIdx.x;
    if (e < EE) atomicAdd(&g_cnt[ei[EE + e]], 1);
}

__global__ __launch_bounds__(512) void scan1_k() {
    __shared__ int wsum[16];
    const int t = threadIdx.x, lane = t & 31, wid = t >> 5;
    const int i = blockIdx.x * 512 + t;
    int v = (i < NN) ? g_cnt[i] : 0;
    int x = v;
    #pragma unroll
    for (int d = 1; d < 32; d <<= 1) {
        int y = __shfl_up_sync(0xffffffffu, x, d);
        if (lane >= d) x += y;
    }
    if (lane == 31) wsum[wid] = x;
    __syncthreads();
    if (wid == 0 && lane < 16) {
        int w = wsum[lane];
        #pragma unroll
        for (int d = 1; d < 16; d <<= 1) {
            int y = __shfl_up_sync(0xffffu, w, d);
            if (lane >= d) w += y;
        }
        wsum[lane] = w;
    }
    __syncthreads();
    int incl = x + (wid ? wsum[wid - 1] : 0);
    if (i < NN) g_off[i] = incl - v;
    if (t == 511) g_bsum[blockIdx.x] = incl;
}

__global__ __launch_bounds__(256) void scan2_k(int nblk) {
    __shared__ int wsum[8];
    const int t = threadIdx.x, lane = t & 31, wid = t >> 5;
    int v = (t < nblk) ? g_bsum[t] : 0;
    int x = v;
    #pragma unroll
    for (int d = 1; d < 32; d <<= 1) {
        int y = __shfl_up_sync(0xffffffffu, x, d);
        if (lane >= d) x += y;
    }
    if (lane == 31) wsum[wid] = x;
    __syncthreads();
    if (wid == 0 && lane < 8) {
        int w = wsum[lane];
        #pragma unroll
        for (int d = 1; d < 8; d <<= 1) {
            int y = __shfl_up_sync(0xffu, w, d);
            if (lane >= d) w += y;
        }
        wsum[lane] = w;
    }
    __syncthreads();
    int incl = x + (wid ? wsum[wid - 1] : 0);
    if (t < nblk) g_bsum[t] = incl - v;
}

__global__ void scan3_k() {
    int i = blockIdx.x * blockDim.x + threadIdx.x;
    if (i < NN) {
        int o = g_off[i] + g_bsum[i >> 9];
        g_off[i] = o;
        g_cur[i] = o;
    }
    if (i == 0) g_off[NN] = EE;
}

__global__ void fill_k(const int* __restrict__ ei) {
    int e = blockIdx.x * blockDim.x + threadIdx.x;
    if (e < EE) {
        int src = ei[e];
        int dst = ei[EE + e];
        int pos = atomicAdd(&g_cur[dst], 1);
        g_srcs[pos] = src;
    }
}

// ---------------- fused aggregation: xo = relu(segsum(y[src]) + r + bias) ----------------
__global__ __launch_bounds__(128) void agg_fused_k(
    const __half* __restrict__ y, const __half* __restrict__ r,
    const float* __restrict__ bias, __half* __restrict__ xo)
{
    const int node = blockIdx.x * 4 + (threadIdx.x >> 5);
    if (node >= NN) return;
    const int lane = threadIdx.x & 31;
    const int s = g_off[node], e = g_off[node + 1];
    float a0 = 0.f, a1 = 0.f, a2 = 0.f, a3 = 0.f;
    int p = s;
    for (; p + 1 < e; p += 2) {
        int s0 = g_srcs[p];
        int s1 = g_srcs[p + 1];
        uint2 u0 = *(const uint2*)(y + (size_t)s0 * HH + lane * 4);
        uint2 u1 = *(const uint2*)(y + (size_t)s1 * HH + lane * 4);
        float2 f;
        f = __half22float2(*(__half2*)&u0.x); a0 += f.x; a1 += f.y;
        f = __half22float2(*(__half2*)&u0.y); a2 += f.x; a3 += f.y;
        f = __half22float2(*(__half2*)&u1.x); a0 += f.x; a1 += f.y;
        f = __half22float2(*(__half2*)&u1.y); a2 += f.x; a3 += f.y;
    }
    if (p < e) {
        uint2 u0 = *(const uint2*)(y + (size_t)g_srcs[p] * HH + lane * 4);
        float2 f;
        f = __half22float2(*(__half2*)&u0.x); a0 += f.x; a1 += f.y;
        f = __half22float2(*(__half2*)&u0.y); a2 += f.x; a3 += f.y;
    }
    uint2 rv = *(const uint2*)(r + (size_t)node * HH + lane * 4);
    float4 bb = *(const float4*)(bias + lane * 4);
    float2 f;
    f = __half22float2(*(__half2*)&rv.x);
    a0 = fmaxf(a0 + f.x + bb.x, 0.f);
    a1 = fmaxf(a1 + f.y + bb.y, 0.f);
    f = __half22float2(*(__half2*)&rv.y);
    a2 = fmaxf(a2 + f.x + bb.z, 0.f);
    a3 = fmaxf(a3 + f.y + bb.w, 0.f);
    uint2 o;
    *(__half2*)&o.x = __floats2half2_rn(a0, a1);
    *(__half2*)&o.y = __floats2half2_rn(a2, a3);
    *(uint2*)(xo + (size_t)node * HH + lane * 4) = o;
}

// ---------------- fp16 MMA helpers ----------------
__device__ __forceinline__ void mma_f16(float* d, const uint32_t* a, const uint32_t* b) {
    asm volatile(
        "mma.sync.aligned.m16n8k16.row.col.f32.f16.f16.f32 "
        "{%0,%1,%2,%3}, {%4,%5,%6,%7}, {%8,%9}, {%0,%1,%2,%3};\n"
        : "+f"(d[0]), "+f"(d[1]), "+f"(d[2]), "+f"(d[3])
        : "r"(a[0]), "r"(a[1]), "r"(a[2]), "r"(a[3]),
          "r"(b[0]), "r"(b[1]));
}

__device__ __forceinline__ void ldsm_x4(uint32_t& r0, uint32_t& r1, uint32_t& r2, uint32_t& r3, uint32_t addr) {
    asm volatile("ldmatrix.sync.aligned.m8n8.x4.shared.b16 {%0,%1,%2,%3}, [%4];"
                 : "=r"(r0), "=r"(r1), "=r"(r2), "=r"(r3) : "r"(addr));
}

__device__ __forceinline__ void ldsm_x4_t(uint32_t& r0, uint32_t& r1, uint32_t& r2, uint32_t& r3, uint32_t addr) {
    asm volatile("ldmatrix.sync.aligned.m8n8.x4.trans.shared.b16 {%0,%1,%2,%3}, [%4];"
                 : "=r"(r0), "=r"(r1), "=r"(r2), "=r"(r3) : "r"(addr));
}

__device__ __forceinline__ void ldsm_x2_t(uint32_t& r0, uint32_t& r1, uint32_t addr) {
    asm volatile("ldmatrix.sync.aligned.m8n8.x2.trans.shared.b16 {%0,%1}, [%2];"
                 : "=r"(r0), "=r"(r1) : "r"(addr));
}

// ---------------- layer GEMM: C = A @ B (half out), M=NN, N=128, K=128 ----------------
#define SA_STRIDE 40
#define SB_STRIDE 136
__global__ __launch_bounds__(256) void gemm_xw_k(
    const float* __restrict__ Af, const __half* __restrict__ Ah, int a_is_f32,
    const float* __restrict__ B1, const float* __restrict__ B2,
    __half* __restrict__ C1, __half* __restrict__ C2)
{
    const float* __restrict__ B = blockIdx.y ? B2 : B1;
    __half* __restrict__ C = blockIdx.y ? C2 : C1;

    __shared__ __half sA[128 * SA_STRIDE];
    __shared__ __half sB[32 * SB_STRIDE];

    const int t    = threadIdx.x;
    const int lane = t & 31;
    const int wid  = t >> 5;
    const int wm   = wid >> 2;
    const int wn   = wid & 3;
    const int m0   = blockIdx.x * 128;

    const uint32_t sa_base = (uint32_t)__cvta_generic_to_shared(sA);
    const uint32_t sb_base = (uint32_t)__cvta_generic_to_shared(sB);

    float acc[4][4][4];
    #pragma unroll
    for (int mt = 0; mt < 4; mt++)
        #pragma unroll
        for (int nt = 0; nt < 4; nt++)
            #pragma unroll
            for (int q = 0; q < 4; q++) acc[mt][nt][q] = 0.f;

    const int li  = lane >> 3;
    const int lr  = lane & 7;
    const int a_row = (li & 1) * 8 + lr;
    const int a_kof = (li >> 1) * 8;
    const int b_krow = (li & 1) * 8 + lr;
    const int b_nof  = (li >> 1) * 8;

    #pragma unroll 1
    for (int s = 0; s < 4; ++s) {
        const int kb = s * 32;

        if (a_is_f32) {
            #pragma unroll
            for (int q = 0; q < 4; ++q) {
                int idx = q * 256 + t;
                int r   = idx >> 3;
                int c4  = (idx & 7) * 4;
                int grow = m0 + r;
                float4 v = (grow < NN)
                    ? *(const float4*)(Af + (size_t)grow * HH + kb + c4)
                    : make_float4(0.f, 0.f, 0.f, 0.f);
                uint2 h;
                *(__half2*)&h.x = __floats2half2_rn(v.x, v.y);
                *(__half2*)&h.y = __floats2half2_rn(v.z, v.w);
                *(uint2*)&sA[r * SA_STRIDE + c4] = h;
            }
        } else {
            #pragma unroll
            for (int q = 0; q < 2; ++q) {
                int idx = q * 256 + t;
                int r   = idx >> 2;
                int c   = (idx & 3) * 8;
                int grow = m0 + r;
                uint4 v = (grow < NN)
                    ? *(const uint4*)(Ah + (size_t)grow * HH + kb + c)
                    : make_uint4(0u, 0u, 0u, 0u);
                *(uint4*)&sA[r * SA_STRIDE + c] = v;
            }
        }
        #pragma unroll
        for (int q = 0; q < 4; ++q) {
            int idx = q * 256 + t;
            int kr  = idx >> 5;
            int c4  = (idx & 31) * 4;
            float4 v = *(const float4*)(B + (size_t)(kb + kr) * 128 + c4);
            uint2 h;
            *(__half2*)&h.x = __floats2half2_rn(v.x, v.y);
            *(__half2*)&h.y = __floats2half2_rn(v.z, v.w);
            *(uint2*)&sB[kr * SB_STRIDE + c4] = h;
        }
        __syncthreads();

        #pragma unroll
        for (int kk = 0; kk < 2; ++kk) {
            const int k0 = kk * 16;
            uint32_t a[4][4], b[4][2];
            #pragma unroll
            for (int mt = 0; mt < 4; ++mt) {
                uint32_t addr = sa_base +
                    ((wm * 64 + mt * 16 + a_row) * SA_STRIDE + k0 + a_kof) * 2;
                ldsm_x4(a[mt][0], a[mt][1], a[mt][2], a[mt][3], addr);
            }
            #pragma unroll
            for (int p = 0; p < 2; ++p) {
                uint32_t addr = sb_base +
                    ((k0 + b_krow) * SB_STRIDE + wn * 32 + p * 16 + b_nof) * 2;
                ldsm_x4_t(b[2 * p][0], b[2 * p][1], b[2 * p + 1][0], b[2 * p + 1][1], addr);
            }
            #pragma unroll
            for (int mt = 0; mt < 4; ++mt)
                #pragma unroll
                for (int nt = 0; nt < 4; ++nt)
                    mma_f16(acc[mt][nt], a[mt], b[nt]);
        }
        __syncthreads();
    }

    const int r0 = m0 + wm * 64 + (lane >> 2);
    const int c0 = wn * 32 + 2 * (lane & 3);
    #pragma unroll
    for (int nt = 0; nt < 4; ++nt) {
        int col = c0 + nt * 8;
        #pragma unroll
        for (int mt = 0; mt < 4; ++mt) {
            int row = r0 + mt * 16;
            if (row < NN)
                *(__half2*)&C[(size_t)row * HH + col] =
                    __floats2half2_rn(acc[mt][nt][0], acc[mt][nt][1]);
            if (row + 8 < NN)
                *(__half2*)&C[(size_t)(row + 8) * HH + col] =
                    __floats2half2_rn(acc[mt][nt][2], acc[mt][nt][3]);
        }
    }
}

// ---------------- logits GEMM (fp16 MMA) + fused log_softmax ----------------
#define LB_STRIDE 40
__global__ __launch_bounds__(256) void gemm_logits_f16_k(
    const float* __restrict__ W, const float* __restrict__ bias,
    float* __restrict__ out)
{
    __shared__ __half sA[256 * SA_STRIDE];
    __shared__ __half sB[32 * LB_STRIDE];

    const int t    = threadIdx.x;
    const int lane = t & 31;
    const int w    = t >> 5;
    const int m0   = blockIdx.x * 256;

    const uint32_t sa_base = (uint32_t)__cvta_generic_to_shared(sA);
    const uint32_t sb_base = (uint32_t)__cvta_generic_to_shared(sB);

    float acc[2][5][4];
    #pragma unroll
    for (int mt = 0; mt < 2; mt++)
        #pragma unroll
        for (int nt = 0; nt < 5; nt++)
            #pragma unroll
            for (int q = 0; q < 4; q++) acc[mt][nt][q] = 0.f;

    const int li  = lane >> 3;
    const int lr  = lane & 7;
    const int a_row = (li & 1) * 8 + lr;
    const int a_kof = (li >> 1) * 8;
    const int b_krow = ((lane >> 3) & 1) * 8 + lr;

    #pragma unroll 1
    for (int k0g = 0; k0g < 256; k0g += 32) {
        const __half* __restrict__ A = (k0g < 128) ? g_x1h : g_x2h;
        const int kb = k0g & 127;
        #pragma unroll
        for (int q = 0; q < 4; ++q) {
            int idx = q * 256 + t;
            int r   = idx >> 2;
            int c   = (idx & 3) * 8;
            int grow = m0 + r;
            uint4 v = (grow < NN)
                ? *(const uint4*)(A + (size_t)grow * HH + kb + c)
                : make_uint4(0u, 0u, 0u, 0u);
            *(uint4*)&sA[r * SA_STRIDE + c] = v;
        }
        #pragma unroll
        for (int q = 0; q < 3; ++q) {
            int idx = q * 256 + t;
            if (idx < 640) {
                int kr = idx / 20, c2 = (idx % 20) * 2;
                float2 v = *(const float2*)(W + (size_t)(k0g + kr) * 40 + c2);
                *(__half2*)&sB[kr * LB_STRIDE + c2] = __floats2half2_rn(v.x, v.y);
            }
        }
        __syncthreads();

        #pragma unroll
        for (int kk = 0; kk < 2; ++kk) {
            const int k0 = kk * 16;
            uint32_t a[2][4], b[5][2];
            #pragma unroll
            for (int mt = 0; mt < 2; ++mt) {
                uint32_t addr = sa_base +
                    ((w * 32 + mt * 16 + a_row) * SA_STRIDE + k0 + a_kof) * 2;
                ldsm_x4(a[mt][0], a[mt][1], a[mt][2], a[mt][3], addr);
            }
            #pragma unroll
            for (int nt = 0; nt < 5; ++nt) {
                uint32_t addr = sb_base +
                    ((k0 + b_krow) * LB_STRIDE + nt * 8) * 2;
                ldsm_x2_t(b[nt][0], b[nt][1], addr);
            }
            #pragma unroll
            for (int mt = 0; mt < 2; ++mt)
                #pragma unroll
                for (int nt = 0; nt < 5; ++nt)
                    mma_f16(acc[mt][nt], a[mt], b[nt]);
        }
        __syncthreads();
    }

    #pragma unroll
    for (int mt = 0; mt < 2; ++mt) {
        float vA[10], vB[10];
        #pragma unroll
        for (int nt = 0; nt < 5; ++nt) {
            #pragma unroll
            for (int j = 0; j < 2; ++j) {
                int c = nt * 8 + 2 * (lane & 3) + j;
                float bb = bias[c];
                vA[nt * 2 + j] = acc[mt][nt][j]     + bb;
                vB[nt * 2 + j] = acc[mt][nt][2 + j] + bb;
            }
        }
        float mA = vA[0], mB = vB[0];
        #pragma unroll
        for (int k = 1; k < 10; ++k) { mA = fmaxf(mA, vA[k]); mB = fmaxf(mB, vB[k]); }
        mA = fmaxf(mA, __shfl_xor_sync(0xffffffffu, mA, 1));
        mA = fmaxf(mA, __shfl_xor_sync(0xffffffffu, mA, 2));
        mB = fmaxf(mB, __shfl_xor_sync(0xffffffffu, mB, 1));
        mB = fmaxf(mB, __shfl_xor_sync(0xffffffffu, mB, 2));
        float eA = 0.f, eB = 0.f;
        #pragma unroll
        for (int k = 0; k < 10; ++k) { eA += expf(vA[k] - mA); eB += expf(vB[k] - mB); }
        eA += __shfl_xor_sync(0xffffffffu, eA, 1);
        eA += __shfl_xor_sync(0xffffffffu, eA, 2);
        eB += __shfl_xor_sync(0xffffffffu, eB, 1);
        eB += __shfl_xor_sync(0xffffffffu, eB, 2);
        float lA = mA + logf(eA), lB = mB + logf(eB);

        int rowA = m0 + w * 32 + mt * 16 + (lane >> 2);
        int rowB = rowA + 8;
        #pragma unroll
        for (int nt = 0; nt < 5; ++nt) {
            int c = nt * 8 + 2 * (lane & 3);
            if (rowA < NN)
                *(float2*)&out[(size_t)rowA * 40 + c] =
                    make_float2(vA[nt * 2] - lA, vA[nt * 2 + 1] - lA);
            if (rowB < NN)
                *(float2*)&out[(size_t)rowB * 40 + c] =
                    make_float2(vB[nt * 2] - lB, vB[nt * 2 + 1] - lB);
        }
    }
}

// ---------------- launch ----------------
extern "C" void kernel_launch(void* const* d_in, const int* in_sizes, int n_in,
                              void* d_out, int out_size) {
    const float* x      = (const float*)d_in[0];
    const int*   ei     = (const int*)  d_in[1];
    const float* Wrel1  = (const float*)d_in[2];
    const float* brel1  = (const float*)d_in[3];
    const float* Wroot1 = (const float*)d_in[4];
    const float* Wrel2  = (const float*)d_in[5];
    const float* brel2  = (const float*)d_in[6];
    const float* Wroot2 = (const float*)d_in[7];
    const float* Wlin   = (const float*)d_in[8];
    const float* blin   = (const float*)d_in[9];
    float* out = (float*)d_out;

    const int nblk = (NN + 511) / 512;

    __half *yh, *rh, *x1h, *x2h;
    cudaGetSymbolAddress((void**)&yh,  g_yh);
    cudaGetSymbolAddress((void**)&rh,  g_rh);
    cudaGetSymbolAddress((void**)&x1h, g_x1h);
    cudaGetSymbolAddress((void**)&x2h, g_x2h);

    // one-time side-stream + events (host-side objects; no device memory)
    static cudaStream_t s_side = nullptr;
    static cudaEvent_t  s_evFork = nullptr, s_evJoin = nullptr;
    if (s_side == nullptr) {
        cudaStreamCreateWithFlags(&s_side, cudaStreamNonBlocking);
        cudaEventCreateWithFlags(&s_evFork, cudaEventDisableTiming);
        cudaEventCreateWithFlags(&s_evJoin, cudaEventDisableTiming);
    }

    dim3 ggrid((NN + 127) / 128, 2);

    // fork: CSR build chain on side stream, concurrent with layer-1 GEMM
    cudaEventRecord(s_evFork, 0);
    cudaStreamWaitEvent(s_side, s_evFork, 0);

    zero_cnt_k<<<(NN + 255) / 256, 256, 0, s_side>>>();
    hist_k<<<(EE + 255) / 256, 256, 0, s_side>>>(ei);
    scan1_k<<<nblk, 512, 0, s_side>>>();
    scan2_k<<<1, 256, 0, s_side>>>(nblk);
    scan3_k<<<(NN + 255) / 256, 256, 0, s_side>>>();
    fill_k<<<(EE + 255) / 256, 256, 0, s_side>>>(ei);
    cudaEventRecord(s_evJoin, s_side);

    // main stream: layer-1 GEMM (independent of CSR)
    gemm_xw_k<<<ggrid, 256>>>(x, nullptr, 1, Wrel1, Wroot1, yh, rh);

    // join: agg needs both CSR and gemm1 output
    cudaStreamWaitEvent(0, s_evJoin, 0);
    agg_fused_k<<<(NN + 3) / 4, 128>>>(yh, rh, brel1, x1h);

    // layer 2
    gemm_xw_k<<<ggrid, 256>>>(nullptr, x1h, 0, Wrel2, Wroot2, yh, rh);
    agg_fused_k<<<(NN + 3) / 4, 128>>>(yh, rh, brel2, x2h);

    // head: logits + log_softmax fused
    gemm_logits_f16_k<<<(NN + 255) / 256, 256>>>(Wlin, blin, out);
}

// round 8
// speedup vs baseline: 3.5324x; 1.0723x over previous
#include <cuda_runtime.h>
#include <cuda_fp16.h>
#include <math.h>
#include <stdint.h>

#define NN 100000
#define EE 1600000
#define HH 128
#define CC 40

// ---- scratch (device globals; no allocation allowed) ----
__device__ __align__(16) __half g_xh  [(size_t)NN * HH];
__device__ __align__(16) __half g_yh  [(size_t)NN * HH];
__device__ __align__(16) __half g_rh  [(size_t)NN * HH];
__device__ __align__(16) __half g_x1h [(size_t)NN * HH];
__device__ __align__(16) __half g_x2h [(size_t)NN * HH];
__device__ __align__(16) __half g_wr1h[HH * HH];
__device__ __align__(16) __half g_wo1h[HH * HH];
__device__ __align__(16) __half g_wr2h[HH * HH];
__device__ __align__(16) __half g_wo2h[HH * HH];
__device__ __align__(16) __half g_wlh [2 * HH * CC];
__device__ int    g_cnt[NN];
__device__ int    g_off[NN + 1];
__device__ int    g_cur[NN];
__device__ int    g_srcs[EE];
__device__ int    g_bsum[256];

// ---------------- CSR build ----------------
__global__ void zero_cnt_k() {
    int i = blockIdx.x * blockDim.x + threadIdx.x;
    if (i < NN) g_cnt[i] = 0;
}

__global__ void hist_k(const int* __restrict__ ei) {
    int e = blockIdx.x * blockDim.x + threadIdx.x;
    if (e < EE) atomicAdd(&g_cnt[ei[EE + e]], 1);
}

__global__ __launch_bounds__(512) void scan1_k() {
    __shared__ int wsum[16];
    const int t = threadIdx.x, lane = t & 31, wid = t >> 5;
    const int i = blockIdx.x * 512 + t;
    int v = (i < NN) ? g_cnt[i] : 0;
    int x = v;
    #pragma unroll
    for (int d = 1; d < 32; d <<= 1) {
        int y = __shfl_up_sync(0xffffffffu, x, d);
        if (lane >= d) x += y;
    }
    if (lane == 31) wsum[wid] = x;
    __syncthreads();
    if (wid == 0 && lane < 16) {
        int w = wsum[lane];
        #pragma unroll
        for (int d = 1; d < 16; d <<= 1) {
            int y = __shfl_up_sync(0xffffu, w, d);
            if (lane >= d) w += y;
        }
        wsum[lane] = w;
    }
    __syncthreads();
    int incl = x + (wid ? wsum[wid - 1] : 0);
    if (i < NN) g_off[i] = incl - v;
    if (t == 511) g_bsum[blockIdx.x] = incl;
}

__global__ __launch_bounds__(256) void scan2_k(int nblk) {
    __shared__ int wsum[8];
    const int t = threadIdx.x, lane = t & 31, wid = t >> 5;
    int v = (t < nblk) ? g_bsum[t] : 0;
    int x = v;
    #pragma unroll
    for (int d = 1; d < 32; d <<= 1) {
        int y = __shfl_up_sync(0xffffffffu, x, d);
        if (lane >= d) x += y;
    }
    if (lane == 31) wsum[wid] = x;
    __syncthreads();
    if (wid == 0 && lane < 8) {
        int w = wsum[lane];
        #pragma unroll
        for (int d = 1; d < 8; d <<= 1) {
            int y = __shfl_up_sync(0xffu, w, d);
            if (lane >= d) w += y;
        }
        wsum[lane] = w;
    }
    __syncthreads();
    int incl = x + (wid ? wsum[wid - 1] : 0);
    if (t < nblk) g_bsum[t] = incl - v;
}

__global__ void scan3_k() {
    int i = blockIdx.x * blockDim.x + threadIdx.x;
    if (i < NN) {
        int o = g_off[i] + g_bsum[i >> 9];
        g_off[i] = o;
        g_cur[i] = o;
    }
    if (i == 0) g_off[NN] = EE;
}

__global__ void fill_k(const int* __restrict__ ei) {
    int e = blockIdx.x * blockDim.x + threadIdx.x;
    if (e < EE) {
        int src = ei[e];
        int dst = ei[EE + e];
        int pos = atomicAdd(&g_cur[dst], 1);
        g_srcs[pos] = src;
    }
}

// ---------------- converts ----------------
__global__ void cvt_x_k(const float* __restrict__ x) {
    int i = blockIdx.x * blockDim.x + threadIdx.x;
    if (i < NN * HH / 4) {
        float4 v = *(const float4*)(x + (size_t)i * 4);
        __half2* o = (__half2*)(g_xh + (size_t)i * 4);
        o[0] = __floats2half2_rn(v.x, v.y);
        o[1] = __floats2half2_rn(v.z, v.w);
    }
}

__global__ void cvt_w_k(const float* __restrict__ w1, const float* __restrict__ w2,
                        const float* __restrict__ w3, const float* __restrict__ w4,
                        const float* __restrict__ w5) {
    int i = blockIdx.x * blockDim.x + threadIdx.x;
    const int NW = HH * HH;          // 16384
    if (i < NW)               g_wr1h[i] = __float2half_rn(w1[i]);
    else if (i < 2 * NW)      g_wo1h[i - NW] = __float2half_rn(w2[i - NW]);
    else if (i < 3 * NW)      g_wr2h[i - 2 * NW] = __float2half_rn(w3[i - 2 * NW]);
    else if (i < 4 * NW)      g_wo2h[i - 3 * NW] = __float2half_rn(w4[i - 3 * NW]);
    else if (i < 4 * NW + 2 * HH * CC) g_wlh[i - 4 * NW] = __float2half_rn(w5[i - 4 * NW]);
}

// ---------------- fused aggregation: xo = relu(segsum(y[src]) + r + bias) ----------------
__global__ __launch_bounds__(128) void agg_fused_k(
    const __half* __restrict__ y, const __half* __restrict__ r,
    const float* __restrict__ bias, __half* __restrict__ xo)
{
    const int node = blockIdx.x * 4 + (threadIdx.x >> 5);
    if (node >= NN) return;
    const int lane = threadIdx.x & 31;
    const int s = g_off[node], e = g_off[node + 1];
    float a0 = 0.f, a1 = 0.f, a2 = 0.f, a3 = 0.f;
    int p = s;
    for (; p + 1 < e; p += 2) {
        int s0 = g_srcs[p];
        int s1 = g_srcs[p + 1];
        uint2 u0 = *(const uint2*)(y + (size_t)s0 * HH + lane * 4);
        uint2 u1 = *(const uint2*)(y + (size_t)s1 * HH + lane * 4);
        float2 f;
        f = __half22float2(*(__half2*)&u0.x); a0 += f.x; a1 += f.y;
        f = __half22float2(*(__half2*)&u0.y); a2 += f.x; a3 += f.y;
        f = __half22float2(*(__half2*)&u1.x); a0 += f.x; a1 += f.y;
        f = __half22float2(*(__half2*)&u1.y); a2 += f.x; a3 += f.y;
    }
    if (p < e) {
        uint2 u0 = *(const uint2*)(y + (size_t)g_srcs[p] * HH + lane * 4);
        float2 f;
        f = __half22float2(*(__half2*)&u0.x); a0 += f.x; a1 += f.y;
        f = __half22float2(*(__half2*)&u0.y); a2 += f.x; a3 += f.y;
    }
    uint2 rv = *(const uint2*)(r + (size_t)node * HH + lane * 4);
    float4 bb = *(const float4*)(bias + lane * 4);
    float2 f;
    f = __half22float2(*(__half2*)&rv.x);
    a0 = fmaxf(a0 + f.x + bb.x, 0.f);
    a1 = fmaxf(a1 + f.y + bb.y, 0.f);
    f = __half22float2(*(__half2*)&rv.y);
    a2 = fmaxf(a2 + f.x + bb.z, 0.f);
    a3 = fmaxf(a3 + f.y + bb.w, 0.f);
    uint2 o;
    *(__half2*)&o.x = __floats2half2_rn(a0, a1);
    *(__half2*)&o.y = __floats2half2_rn(a2, a3);
    *(uint2*)(xo + (size_t)node * HH + lane * 4) = o;
}

// ---------------- fp16 MMA + cp.async helpers ----------------
__device__ __forceinline__ void mma_f16(float* d, const uint32_t* a, const uint32_t* b) {
    asm volatile(
        "mma.sync.aligned.m16n8k16.row.col.f32.f16.f16.f32 "
        "{%0,%1,%2,%3}, {%4,%5,%6,%7}, {%8,%9}, {%0,%1,%2,%3};\n"
        : "+f"(d[0]), "+f"(d[1]), "+f"(d[2]), "+f"(d[3])
        : "r"(a[0]), "r"(a[1]), "r"(a[2]), "r"(a[3]),
          "r"(b[0]), "r"(b[1]));
}

__device__ __forceinline__ void ldsm_x4(uint32_t& r0, uint32_t& r1, uint32_t& r2, uint32_t& r3, uint32_t addr) {
    asm volatile("ldmatrix.sync.aligned.m8n8.x4.shared.b16 {%0,%1,%2,%3}, [%4];"
                 : "=r"(r0), "=r"(r1), "=r"(r2), "=r"(r3) : "r"(addr));
}

__device__ __forceinline__ void ldsm_x4_t(uint32_t& r0, uint32_t& r1, uint32_t& r2, uint32_t& r3, uint32_t addr) {
    asm volatile("ldmatrix.sync.aligned.m8n8.x4.trans.shared.b16 {%0,%1,%2,%3}, [%4];"
                 : "=r"(r0), "=r"(r1), "=r"(r2), "=r"(r3) : "r"(addr));
}

__device__ __forceinline__ void ldsm_x2_t(uint32_t& r0, uint32_t& r1, uint32_t addr) {
    asm volatile("ldmatrix.sync.aligned.m8n8.x2.trans.shared.b16 {%0,%1}, [%2];"
                 : "=r"(r0), "=r"(r1) : "r"(addr));
}

__device__ __forceinline__ void cp16(uint32_t saddr, const void* gaddr, bool valid) {
    int sz = valid ? 16 : 0;
    asm volatile("cp.async.cg.shared.global [%0], [%1], 16, %2;\n"
                 :: "r"(saddr), "l"(gaddr), "r"(sz));
}
__device__ __forceinline__ void cp_commit() { asm volatile("cp.async.commit_group;\n"); }
template <int N>
__device__ __forceinline__ void cp_wait() { asm volatile("cp.async.wait_group %0;\n" :: "n"(N)); }

// ---------------- layer GEMM (pipelined, all fp16): C = A @ B, M=NN, N=128, K=128 ----------------
#define SA_STRIDE 40    // halfs (80B rows, x16 aligned, conflict-free LDSM)
#define SB_STRIDE 136   // halfs (272B rows)
#define ABUF (128 * SA_STRIDE)
#define BBUF (32 * SB_STRIDE)
__global__ __launch_bounds__(256) void gemm_xw_k(
    const __half* __restrict__ A,
    const __half* __restrict__ B1h, const __half* __restrict__ B2h,
    __half* __restrict__ C1, __half* __restrict__ C2)
{
    const __half* __restrict__ B = blockIdx.y ? B2h : B1h;
    __half* __restrict__ C = blockIdx.y ? C2 : C1;

    __shared__ __half sA[2 * ABUF];
    __shared__ __half sB[2 * BBUF];

    const int t    = threadIdx.x;
    const int lane = t & 31;
    const int wid  = t >> 5;
    const int wm   = wid >> 2;
    const int wn   = wid & 3;
    const int m0   = blockIdx.x * 128;

    const uint32_t sa_base = (uint32_t)__cvta_generic_to_shared(sA);
    const uint32_t sb_base = (uint32_t)__cvta_generic_to_shared(sB);

    float acc[4][4][4];
    #pragma unroll
    for (int mt = 0; mt < 4; mt++)
        #pragma unroll
        for (int nt = 0; nt < 4; nt++)
            #pragma unroll
            for (int q = 0; q < 4; q++) acc[mt][nt][q] = 0.f;

    const int li  = lane >> 3;
    const int lr  = lane & 7;
    const int a_row = (li & 1) * 8 + lr;
    const int a_kof = (li >> 1) * 8;
    const int b_krow = (li & 1) * 8 + lr;
    const int b_nof  = (li >> 1) * 8;

    // per-thread staging coords (2 x 16B chunks each for A and B)
    // A: idx 0..511 -> r=idx>>2 (0..127), c=(idx&3)*8
    // B: idx 0..511 -> kr=idx>>4 (0..31), cB=(idx&15)*8
    auto stage = [&](int s, int b) {
        const int kb = s * 32;
        #pragma unroll
        for (int q = 0; q < 2; ++q) {
            int idx = q * 256 + t;
            int r = idx >> 2, c = (idx & 3) * 8;
            int grow = m0 + r;
            int gc = (grow < NN) ? grow : (NN - 1);
            cp16(sa_base + (b * ABUF + r * SA_STRIDE + c) * 2,
                 A + (size_t)gc * HH + kb + c, grow < NN);
            int kr = idx >> 4, cB = (idx & 15) * 8;
            cp16(sb_base + (b * BBUF + kr * SB_STRIDE + cB) * 2,
                 B + (size_t)(kb + kr) * 128 + cB, true);
        }
        cp_commit();
    };

    stage(0, 0);
    #pragma unroll
    for (int s = 0; s < 4; ++s) {
        if (s < 3) { stage(s + 1, (s + 1) & 1); cp_wait<1>(); }
        else       { cp_wait<0>(); }
        __syncthreads();

        const int buf = s & 1;
        #pragma unroll
        for (int kk = 0; kk < 2; ++kk) {
            const int k0 = kk * 16;
            uint32_t a[4][4], b[4][2];
            #pragma unroll
            for (int mt = 0; mt < 4; ++mt) {
                uint32_t addr = sa_base +
                    (buf * ABUF + (wm * 64 + mt * 16 + a_row) * SA_STRIDE + k0 + a_kof) * 2;
                ldsm_x4(a[mt][0], a[mt][1], a[mt][2], a[mt][3], addr);
            }
            #pragma unroll
            for (int p = 0; p < 2; ++p) {
                uint32_t addr = sb_base +
                    (buf * BBUF + (k0 + b_krow) * SB_STRIDE + wn * 32 + p * 16 + b_nof) * 2;
                ldsm_x4_t(b[2 * p][0], b[2 * p][1], b[2 * p + 1][0], b[2 * p + 1][1], addr);
            }
            #pragma unroll
            for (int mt = 0; mt < 4; ++mt)
                #pragma unroll
                for (int nt = 0; nt < 4; ++nt)
                    mma_f16(acc[mt][nt], a[mt], b[nt]);
        }
        __syncthreads();
    }

    const int r0 = m0 + wm * 64 + (lane >> 2);
    const int c0 = wn * 32 + 2 * (lane & 3);
    #pragma unroll
    for (int nt = 0; nt < 4; ++nt) {
        int col = c0 + nt * 8;
        #pragma unroll
        for (int mt = 0; mt < 4; ++mt) {
            int row = r0 + mt * 16;
            if (row < NN)
                *(__half2*)&C[(size_t)row * HH + col] =
                    __floats2half2_rn(acc[mt][nt][0], acc[mt][nt][1]);
            if (row + 8 < NN)
                *(__half2*)&C[(size_t)(row + 8) * HH + col] =
                    __floats2half2_rn(acc[mt][nt][2], acc[mt][nt][3]);
        }
    }
}

// ---------------- logits GEMM (pipelined fp16) + fused log_softmax ----------------
#define LB_STRIDE 40
#define LABUF (256 * SA_STRIDE)
#define LBBUF (32 * LB_STRIDE)
__global__ __launch_bounds__(256) void gemm_logits_f16_k(
    const float* __restrict__ bias, float* __restrict__ out)
{
    __shared__ __half sA[2 * LABUF];
    __shared__ __half sB[2 * LBBUF];

    const int t    = threadIdx.x;
    const int lane = t & 31;
    const int w    = t >> 5;
    const int m0   = blockIdx.x * 256;

    const uint32_t sa_base = (uint32_t)__cvta_generic_to_shared(sA);
    const uint32_t sb_base = (uint32_t)__cvta_generic_to_shared(sB);

    float acc[2][5][4];
    #pragma unroll
    for (int mt = 0; mt < 2; mt++)
        #pragma unroll
        for (int nt = 0; nt < 5; nt++)
            #pragma unroll
            for (int q = 0; q < 4; q++) acc[mt][nt][q] = 0.f;

    const int li  = lane >> 3;
    const int lr  = lane & 7;
    const int a_row = (li & 1) * 8 + lr;
    const int a_kof = (li >> 1) * 8;
    const int b_krow = ((lane >> 3) & 1) * 8 + lr;

    // A: 256x32 halfs = 1024 chunks, 4/thread. B: 32x40 halfs = 160 chunks.
    auto stage = [&](int s, int b) {
        const __half* __restrict__ A = (s < 4) ? g_x1h : g_x2h;
        const int kb = (s & 3) * 32;
        #pragma unroll
        for (int q = 0; q < 4; ++q) {
            int idx = q * 256 + t;
            int r = idx >> 2, c = (idx & 3) * 8;
            int grow = m0 + r;
            int gc = (grow < NN) ? grow : (NN - 1);
            cp16(sa_base + (b * LABUF + r * SA_STRIDE + c) * 2,
                 A + (size_t)gc * HH + kb + c, grow < NN);
        }
        if (t < 160) {
            int kr = t / 5, cB = (t % 5) * 8;
            cp16(sb_base + (b * LBBUF + kr * LB_STRIDE + cB) * 2,
                 g_wlh + (size_t)(s * 32 + kr) * 40 + cB, true);
        }
        cp_commit();
    };

    stage(0, 0);
    #pragma unroll
    for (int s = 0; s < 8; ++s) {
        if (s < 7) { stage(s + 1, (s + 1) & 1); cp_wait<1>(); }
        else       { cp_wait<0>(); }
        __syncthreads();

        const int buf = s & 1;
        #pragma unroll
        for (int kk = 0; kk < 2; ++kk) {
            const int k0 = kk * 16;
            uint32_t a[2][4], b[5][2];
            #pragma unroll
            for (int mt = 0; mt < 2; ++mt) {
                uint32_t addr = sa_base +
                    (buf * LABUF + (w * 32 + mt * 16 + a_row) * SA_STRIDE + k0 + a_kof) * 2;
                ldsm_x4(a[mt][0], a[mt][1], a[mt][2], a[mt][3], addr);
            }
            #pragma unroll
            for (int nt = 0; nt < 5; ++nt) {
                uint32_t addr = sb_base +
                    (buf * LBBUF + (k0 + b_krow) * LB_STRIDE + nt * 8) * 2;
                ldsm_x2_t(b[nt][0], b[nt][1], addr);
            }
            #pragma unroll
            for (int mt = 0; mt < 2; ++mt)
                #pragma unroll
                for (int nt = 0; nt < 5; ++nt)
                    mma_f16(acc[mt][nt], a[mt], b[nt]);
        }
        __syncthreads();
    }

    #pragma unroll
    for (int mt = 0; mt < 2; ++mt) {
        float vA[10], vB[10];
        #pragma unroll
        for (int nt = 0; nt < 5; ++nt) {
            #pragma unroll
            for (int j = 0; j < 2; ++j) {
                int c = nt * 8 + 2 * (lane & 3) + j;
                float bb = bias[c];
                vA[nt * 2 + j] = acc[mt][nt][j]     + bb;
                vB[nt * 2 + j] = acc[mt][nt][2 + j] + bb;
            }
        }
        float mA = vA[0], mB = vB[0];
        #pragma unroll
        for (int k = 1; k < 10; ++k) { mA = fmaxf(mA, vA[k]); mB = fmaxf(mB, vB[k]); }
        mA = fmaxf(mA, __shfl_xor_sync(0xffffffffu, mA, 1));
        mA = fmaxf(mA, __shfl_xor_sync(0xffffffffu, mA, 2));
        mB = fmaxf(mB, __shfl_xor_sync(0xffffffffu, mB, 1));
        mB = fmaxf(mB, __shfl_xor_sync(0xffffffffu, mB, 2));
        float eA = 0.f, eB = 0.f;
        #pragma unroll
        for (int k = 0; k < 10; ++k) { eA += expf(vA[k] - mA); eB += expf(vB[k] - mB); }
        eA += __shfl_xor_sync(0xffffffffu, eA, 1);
        eA += __shfl_xor_sync(0xffffffffu, eA, 2);
        eB += __shfl_xor_sync(0xffffffffu, eB, 1);
        eB += __shfl_xor_sync(0xffffffffu, eB, 2);
        float lA = mA + logf(eA), lB = mB + logf(eB);

        int rowA = m0 + w * 32 + mt * 16 + (lane >> 2);
        int rowB = rowA + 8;
        #pragma unroll
        for (int nt = 0; nt < 5; ++nt) {
            int c = nt * 8 + 2 * (lane & 3);
            if (rowA < NN)
                *(float2*)&out[(size_t)rowA * 40 + c] =
                    make_float2(vA[nt * 2] - lA, vA[nt * 2 + 1] - lA);
            if (rowB < NN)
                *(float2*)&out[(size_t)rowB * 40 + c] =
                    make_float2(vB[nt * 2] - lB, vB[nt * 2 + 1] - lB);
        }
    }
}

// ---------------- launch ----------------
extern "C" void kernel_launch(void* const* d_in, const int* in_sizes, int n_in,
                              void* d_out, int out_size) {
    const float* x      = (const float*)d_in[0];
    const int*   ei     = (const int*)  d_in[1];
    const float* Wrel1  = (const float*)d_in[2];
    const float* brel1  = (const float*)d_in[3];
    const float* Wroot1 = (const float*)d_in[4];
    const float* Wrel2  = (const float*)d_in[5];
    const float* brel2  = (const float*)d_in[6];
    const float* Wroot2 = (const float*)d_in[7];
    const float* Wlin   = (const float*)d_in[8];
    const float* blin   = (const float*)d_in[9];
    float* out = (float*)d_out;

    const int nblk = (NN + 511) / 512;

    __half *xh, *yh, *rh, *x1h, *x2h, *wr1, *wo1, *wr2, *wo2;
    cudaGetSymbolAddress((void**)&xh,  g_xh);
    cudaGetSymbolAddress((void**)&yh,  g_yh);
    cudaGetSymbolAddress((void**)&rh,  g_rh);
    cudaGetSymbolAddress((void**)&x1h, g_x1h);
    cudaGetSymbolAddress((void**)&x2h, g_x2h);
    cudaGetSymbolAddress((void**)&wr1, g_wr1h);
    cudaGetSymbolAddress((void**)&wo1, g_wo1h);
    cudaGetSymbolAddress((void**)&wr2, g_wr2h);
    cudaGetSymbolAddress((void**)&wo2, g_wo2h);

    static cudaStream_t s_side = nullptr;
    static cudaEvent_t  s_evFork = nullptr, s_evJoin = nullptr;
    if (s_side == nullptr) {
        cudaStreamCreateWithFlags(&s_side, cudaStreamNonBlocking);
        cudaEventCreateWithFlags(&s_evFork, cudaEventDisableTiming);
        cudaEventCreateWithFlags(&s_evJoin, cudaEventDisableTiming);
    }

    dim3 ggrid((NN + 127) / 128, 2);

    // fork: CSR build on side stream
    cudaEventRecord(s_evFork, 0);
    cudaStreamWaitEvent(s_side, s_evFork, 0);
    zero_cnt_k<<<(NN + 255) / 256, 256, 0, s_side>>>();
    hist_k<<<(EE + 255) / 256, 256, 0, s_side>>>(ei);
    scan1_k<<<nblk, 512, 0, s_side>>>();
    scan2_k<<<1, 256, 0, s_side>>>(nblk);
    scan3_k<<<(NN + 255) / 256, 256, 0, s_side>>>();
    fill_k<<<(EE + 255) / 256, 256, 0, s_side>>>(ei);
    cudaEventRecord(s_evJoin, s_side);

    // main: converts (hidden under CSR) + layer-1 GEMM
    cvt_w_k<<<(4 * HH * HH + 2 * HH * CC + 255) / 256, 256>>>(Wrel1, Wroot1, Wrel2, Wroot2, Wlin);
    cvt_x_k<<<(NN * HH / 4 + 255) / 256, 256>>>(x);
    gemm_xw_k<<<ggrid, 256>>>(xh, wr1, wo1, yh, rh);

    // join: agg needs CSR + gemm1
    cudaStreamWaitEvent(0, s_evJoin, 0);
    agg_fused_k<<<(NN + 3) / 4, 128>>>(yh, rh, brel1, x1h);

    // layer 2
    gemm_xw_k<<<ggrid, 256>>>(x1h, wr2, wo2, yh, rh);
    agg_fused_k<<<(NN + 3) / 4, 128>>>(yh, rh, brel2, x2h);

    // head
    gemm_logits_f16_k<<<(NN + 255) / 256, 256>>>(blin, out);
}